// round 1
// baseline (speedup 1.0000x reference)
#include <cuda_runtime.h>
#include <cuda_bf16.h>
#include <math.h>

// ---------------------------------------------------------------------------
// Problem constants
// ---------------------------------------------------------------------------
constexpr int BATCH   = 2;
constexpr int SEQ     = 2048;
constexpr int DMODEL  = 2048;
constexpr int DFF     = 8192;
constexpr int NHEADS  = 16;
constexpr int NKV     = 8;
constexpr int HD      = 128;
constexpr int DKV     = NKV * HD;      // 1024
constexpr int TOK     = BATCH * SEQ;   // 4096
constexpr float EPSV  = 1e-5f;
constexpr float SM_SCALE = 0.08838834764831845f; // 128^-0.5

// ---------------------------------------------------------------------------
// Scratch (device globals; allocation in kernel_launch is forbidden)
// ---------------------------------------------------------------------------
__device__ float g_x1   [(size_t)TOK * DMODEL];
__device__ float g_q    [(size_t)TOK * DMODEL];
__device__ float g_k    [(size_t)TOK * DKV];
__device__ float g_v    [(size_t)TOK * DKV];
__device__ float g_scores[(size_t)BATCH * NHEADS * SEQ * SEQ]; // 536 MB
__device__ float g_ctx  [(size_t)TOK * DMODEL];
__device__ float g_h2   [(size_t)TOK * DMODEL];
__device__ float g_x2   [(size_t)TOK * DMODEL];
__device__ float g_gate [(size_t)TOK * DFF];
__device__ float g_up   [(size_t)TOK * DFF];

// ---------------------------------------------------------------------------
// Tiled SGEMM body: C[M,N] = A * op(B) (+ R), fp32.
//  NN: B is [K,N] row-major.  NT: B is [N,K] row-major (C = A * B^T).
//  Tile: 128x128x16, 256 threads, 8x8 per-thread micro-tile (split 4+4 so
//  operand fetches are contiguous float4 -> conflict-free LDS.128).
//  All dims assumed divisible by tile sizes (true for every call here).
// ---------------------------------------------------------------------------
constexpr int BM = 128, BN = 128, BK = 16;

template <bool NT>
__device__ __forceinline__ void gemm_body(
    const float* __restrict__ A, const float* __restrict__ B,
    const float* __restrict__ R, float* __restrict__ C,
    int K, int lda, int ldb, int ldc)
{
    __shared__ float As[BK][BM];
    __shared__ float Bs[BK][BN];

    const int tid = threadIdx.x;
    const int tx  = tid & 15;        // 0..15 -> N
    const int ty  = tid >> 4;        // 0..15 -> M
    const int m0  = blockIdx.y * BM;
    const int n0  = blockIdx.x * BN;

    float acc[8][8];
    #pragma unroll
    for (int i = 0; i < 8; i++)
        #pragma unroll
        for (int j = 0; j < 8; j++) acc[i][j] = 0.f;

    for (int k0 = 0; k0 < K; k0 += BK) {
        // ---- load A tile [BM x BK], store transposed As[k][m]
        #pragma unroll
        for (int it = 0; it < 2; it++) {
            int s   = tid + it * 256;          // 0..511
            int row = s >> 2;                  // 0..127
            int kc  = (s & 3) << 2;            // 0,4,8,12
            float4 v = *reinterpret_cast<const float4*>(
                A + (long)(m0 + row) * lda + k0 + kc);
            As[kc + 0][row] = v.x;
            As[kc + 1][row] = v.y;
            As[kc + 2][row] = v.z;
            As[kc + 3][row] = v.w;
        }
        // ---- load B tile -> Bs[k][n]
        if (NT) {
            // B is [N,K]: load rows of B, transpose into Bs
            #pragma unroll
            for (int it = 0; it < 2; it++) {
                int s    = tid + it * 256;
                int nrow = s >> 2;             // 0..127
                int kc   = (s & 3) << 2;
                float4 v = *reinterpret_cast<const float4*>(
                    B + (long)(n0 + nrow) * ldb + k0 + kc);
                Bs[kc + 0][nrow] = v.x;
                Bs[kc + 1][nrow] = v.y;
                Bs[kc + 2][nrow] = v.z;
                Bs[kc + 3][nrow] = v.w;
            }
        } else {
            #pragma unroll
            for (int it = 0; it < 2; it++) {
                int s  = tid + it * 256;
                int kr = s >> 5;               // 0..15
                int nc = (s & 31) << 2;        // 0..124
                *reinterpret_cast<float4*>(&Bs[kr][nc]) =
                    *reinterpret_cast<const float4*>(
                        B + (long)(k0 + kr) * ldb + n0 + nc);
            }
        }
        __syncthreads();

        #pragma unroll
        for (int kk = 0; kk < BK; kk++) {
            float4 a0 = *reinterpret_cast<const float4*>(&As[kk][ty * 4]);
            float4 a1 = *reinterpret_cast<const float4*>(&As[kk][64 + ty * 4]);
            float4 b0 = *reinterpret_cast<const float4*>(&Bs[kk][tx * 4]);
            float4 b1 = *reinterpret_cast<const float4*>(&Bs[kk][64 + tx * 4]);
            float a[8] = {a0.x, a0.y, a0.z, a0.w, a1.x, a1.y, a1.z, a1.w};
            float b[8] = {b0.x, b0.y, b0.z, b0.w, b1.x, b1.y, b1.z, b1.w};
            #pragma unroll
            for (int i = 0; i < 8; i++)
                #pragma unroll
                for (int j = 0; j < 8; j++)
                    acc[i][j] = fmaf(a[i], b[j], acc[i][j]);
        }
        __syncthreads();
    }

    // ---- epilogue (optional residual add), float4 stores
    #pragma unroll
    for (int half = 0; half < 2; half++) {
        #pragma unroll
        for (int i = 0; i < 4; i++) {
            int row = m0 + half * 64 + ty * 4 + i;
            float* cp = C + (long)row * ldc + n0;
            float4 r0, r1;
            int ai = half * 4 + i;
            r0.x = acc[ai][0]; r0.y = acc[ai][1]; r0.z = acc[ai][2]; r0.w = acc[ai][3];
            r1.x = acc[ai][4]; r1.y = acc[ai][5]; r1.z = acc[ai][6]; r1.w = acc[ai][7];
            if (R) {
                const float* rp = R + (long)row * ldc + n0;
                float4 q0 = *reinterpret_cast<const float4*>(rp + tx * 4);
                float4 q1 = *reinterpret_cast<const float4*>(rp + 64 + tx * 4);
                r0.x += q0.x; r0.y += q0.y; r0.z += q0.z; r0.w += q0.w;
                r1.x += q1.x; r1.y += q1.y; r1.z += q1.z; r1.w += q1.w;
            }
            *reinterpret_cast<float4*>(cp + tx * 4)      = r0;
            *reinterpret_cast<float4*>(cp + 64 + tx * 4) = r1;
        }
    }
}

__global__ __launch_bounds__(256, 2) void sgemm_nn_kernel(
    const float* __restrict__ A, const float* __restrict__ B,
    const float* __restrict__ R, float* __restrict__ C,
    int K, int lda, int ldb, int ldc)
{
    gemm_body<false>(A, B, R, C, K, lda, ldb, ldc);
}

// scores[z=(b*16+h)][q][k] = Q_bh[q,:] . K_b(h/2)[k,:]   (scale applied in softmax)
__global__ __launch_bounds__(256, 2) void scores_gemm_kernel()
{
    int z  = blockIdx.z;
    int b  = z >> 4;
    int h  = z & 15;
    int kh = h >> 1;
    const float* A  = g_q + (long)b * SEQ * DMODEL + h * HD;
    const float* Bp = g_k + (long)b * SEQ * DKV + kh * HD;
    float*       Cp = g_scores + (long)z * SEQ * SEQ;
    gemm_body<true>(A, Bp, nullptr, Cp, HD, DMODEL, DKV, SEQ);
}

// ctx[b,s, h*128+d] = sum_k P_bh[s,k] * V_b(h/2)[k,d]
__global__ __launch_bounds__(256, 2) void pv_gemm_kernel()
{
    int z  = blockIdx.z;
    int b  = z >> 4;
    int h  = z & 15;
    int kh = h >> 1;
    const float* A  = g_scores + (long)z * SEQ * SEQ;
    const float* Bp = g_v + (long)b * SEQ * DKV + kh * HD;
    float*       Cp = g_ctx + (long)b * SEQ * DMODEL + h * HD;
    gemm_body<false>(A, Bp, nullptr, Cp, SEQ, SEQ, DKV, DMODEL);
}

// ---------------------------------------------------------------------------
// RMSNorm: one block per row (D=2048), 256 threads x 8 elems
// ---------------------------------------------------------------------------
__device__ __forceinline__ float block_reduce_sum(float v)
{
    __shared__ float red[32];
    int lid = threadIdx.x & 31, wid = threadIdx.x >> 5;
    #pragma unroll
    for (int o = 16; o; o >>= 1) v += __shfl_xor_sync(0xffffffffu, v, o);
    if (lid == 0) red[wid] = v;
    __syncthreads();
    v = (threadIdx.x < (blockDim.x >> 5)) ? red[threadIdx.x] : 0.f;
    if (wid == 0) {
        #pragma unroll
        for (int o = 16; o; o >>= 1) v += __shfl_xor_sync(0xffffffffu, v, o);
        if (lid == 0) red[0] = v;
    }
    __syncthreads();
    return red[0];
}

__device__ __forceinline__ float block_reduce_max(float v)
{
    __shared__ float red[32];
    int lid = threadIdx.x & 31, wid = threadIdx.x >> 5;
    #pragma unroll
    for (int o = 16; o; o >>= 1) v = fmaxf(v, __shfl_xor_sync(0xffffffffu, v, o));
    if (lid == 0) red[wid] = v;
    __syncthreads();
    v = (threadIdx.x < (blockDim.x >> 5)) ? red[threadIdx.x] : -INFINITY;
    if (wid == 0) {
        #pragma unroll
        for (int o = 16; o; o >>= 1) v = fmaxf(v, __shfl_xor_sync(0xffffffffu, v, o));
        if (lid == 0) red[0] = v;
    }
    __syncthreads();
    return red[0];
}

__global__ __launch_bounds__(256) void rmsnorm_kernel(
    const float* __restrict__ x, const float* __restrict__ w,
    float* __restrict__ out)
{
    long row = blockIdx.x;
    const float* xr = x + row * DMODEL;
    float* outr = out + row * DMODEL;
    float vals[8];
    float ss = 0.f;
    #pragma unroll
    for (int i = 0; i < 8; i++) {
        int idx = threadIdx.x + i * 256;
        vals[i] = xr[idx];
        ss = fmaf(vals[i], vals[i], ss);
    }
    float total = block_reduce_sum(ss);
    float rstd = rsqrtf(total * (1.0f / DMODEL) + EPSV);
    #pragma unroll
    for (int i = 0; i < 8; i++) {
        int idx = threadIdx.x + i * 256;
        outr[idx] = vals[i] * rstd * w[idx];
    }
}

// ---------------------------------------------------------------------------
// RoPE (in-place, HF style): out[j] = e*c - o*s ; out[64+j] = e*s + o*c
// where e = x[2j], o = x[2j+1]. One 64-thread block per (token, head).
// ---------------------------------------------------------------------------
__global__ __launch_bounds__(64) void rotary_kernel(
    float* __restrict__ x, const float* __restrict__ cs,
    const float* __restrict__ sn, int ld)
{
    long base = (long)blockIdx.x * ld + blockIdx.y * HD;
    int j = threadIdx.x;                    // 0..63
    float e = x[base + 2 * j];
    float o = x[base + 2 * j + 1];
    float c = cs[(long)blockIdx.x * 64 + j];
    float s = sn[(long)blockIdx.x * 64 + j];
    __syncthreads();                        // all reads before any write
    x[base + j]      = e * c - o * s;
    x[base + 64 + j] = e * s + o * c;
}

// ---------------------------------------------------------------------------
// Softmax over score rows (applies scale and additive mask), single pass.
// grid = (SEQ, B*H), block = 256, each thread owns 8 elems in registers.
// ---------------------------------------------------------------------------
__global__ __launch_bounds__(256) void softmax_kernel(const float* __restrict__ mask)
{
    int z = blockIdx.y;
    int b = z >> 4;
    long row = blockIdx.x;
    float* srow = g_scores + ((long)z * SEQ + row) * SEQ;
    const float* mrow = mask + ((long)b * SEQ + row) * SEQ;

    float v[8];
    float mx = -INFINITY;
    #pragma unroll
    for (int i = 0; i < 8; i++) {
        int idx = threadIdx.x + i * 256;
        v[i] = fmaf(srow[idx], SM_SCALE, mrow[idx]);
        mx = fmaxf(mx, v[i]);
    }
    float bm = block_reduce_max(mx);
    float sum = 0.f;
    #pragma unroll
    for (int i = 0; i < 8; i++) {
        v[i] = expf(v[i] - bm);
        sum += v[i];
    }
    float total = block_reduce_sum(sum);
    float inv = 1.0f / total;
    #pragma unroll
    for (int i = 0; i < 8; i++) {
        int idx = threadIdx.x + i * 256;
        srow[idx] = v[i] * inv;
    }
}

// ---------------------------------------------------------------------------
// SwiGLU gate: gate <- silu(gate) * up
// ---------------------------------------------------------------------------
__global__ __launch_bounds__(256) void silu_mul_kernel(long n)
{
    long i = (long)blockIdx.x * blockDim.x + threadIdx.x;
    if (i < n) {
        float g = g_gate[i];
        float u = g_up[i];
        g_gate[i] = u * g / (1.0f + expf(-g));
    }
}

// ---------------------------------------------------------------------------
// Launch
// ---------------------------------------------------------------------------
extern "C" void kernel_launch(void* const* d_in, const int* in_sizes, int n_in,
                              void* d_out, int out_size)
{
    const float* hs   = (const float*)d_in[0];
    const float* cosp = (const float*)d_in[1];
    const float* sinp = (const float*)d_in[2];
    const float* mask = (const float*)d_in[3];
    const float* wq   = (const float*)d_in[4];
    const float* wk   = (const float*)d_in[5];
    const float* wv   = (const float*)d_in[6];
    const float* wo   = (const float*)d_in[7];
    const float* wg   = (const float*)d_in[8];
    const float* wu   = (const float*)d_in[9];
    const float* wd   = (const float*)d_in[10];
    const float* ln1  = (const float*)d_in[11];
    const float* ln2  = (const float*)d_in[12];
    float* out = (float*)d_out;

    float *x1, *q, *k, *v, *ctx, *h2, *x2, *gate, *up;
    cudaGetSymbolAddress((void**)&x1,   g_x1);
    cudaGetSymbolAddress((void**)&q,    g_q);
    cudaGetSymbolAddress((void**)&k,    g_k);
    cudaGetSymbolAddress((void**)&v,    g_v);
    cudaGetSymbolAddress((void**)&ctx,  g_ctx);
    cudaGetSymbolAddress((void**)&h2,   g_h2);
    cudaGetSymbolAddress((void**)&x2,   g_x2);
    cudaGetSymbolAddress((void**)&gate, g_gate);
    cudaGetSymbolAddress((void**)&up,   g_up);

    // 1) x1 = rmsnorm(h, ln1)
    rmsnorm_kernel<<<TOK, 256>>>(hs, ln1, x1);

    // 2) q/k/v projections
    sgemm_nn_kernel<<<dim3(DMODEL / BN, TOK / BM), 256>>>(x1, wq, nullptr, q,
        DMODEL, DMODEL, DMODEL, DMODEL);
    sgemm_nn_kernel<<<dim3(DKV / BN, TOK / BM), 256>>>(x1, wk, nullptr, k,
        DMODEL, DMODEL, DKV, DKV);
    sgemm_nn_kernel<<<dim3(DKV / BN, TOK / BM), 256>>>(x1, wv, nullptr, v,
        DMODEL, DMODEL, DKV, DKV);

    // 3) RoPE on q and k
    rotary_kernel<<<dim3(TOK, NHEADS), 64>>>(q, cosp, sinp, DMODEL);
    rotary_kernel<<<dim3(TOK, NKV),    64>>>(k, cosp, sinp, DKV);

    // 4) scores = Q K^T  (batched over b,h)
    scores_gemm_kernel<<<dim3(SEQ / BN, SEQ / BM, BATCH * NHEADS), 256>>>();

    // 5) softmax (scale + mask folded in)
    softmax_kernel<<<dim3(SEQ, BATCH * NHEADS), 256>>>(mask);

    // 6) ctx = P @ V  (writes [b,s,h,d] layout)
    pv_gemm_kernel<<<dim3(1, SEQ / BM, BATCH * NHEADS), 256>>>();

    // 7) h2 = hs + ctx @ wo
    sgemm_nn_kernel<<<dim3(DMODEL / BN, TOK / BM), 256>>>(ctx, wo, hs, h2,
        DMODEL, DMODEL, DMODEL, DMODEL);

    // 8) x2 = rmsnorm(h2, ln2)
    rmsnorm_kernel<<<TOK, 256>>>(h2, ln2, x2);

    // 9) MLP
    sgemm_nn_kernel<<<dim3(DFF / BN, TOK / BM), 256>>>(x2, wg, nullptr, gate,
        DMODEL, DMODEL, DFF, DFF);
    sgemm_nn_kernel<<<dim3(DFF / BN, TOK / BM), 256>>>(x2, wu, nullptr, up,
        DMODEL, DMODEL, DFF, DFF);

    long n = (long)TOK * DFF;
    silu_mul_kernel<<<(unsigned)((n + 255) / 256), 256>>>(n);

    // 10) out = h2 + (silu(gate)*up) @ wd
    sgemm_nn_kernel<<<dim3(DMODEL / BN, TOK / BM), 256>>>(gate, wd, h2, out,
        DFF, DFF, DMODEL, DMODEL);
}

// round 2
// speedup vs baseline: 1.0004x; 1.0004x over previous
#include <cuda_runtime.h>
#include <cuda_bf16.h>
#include <math.h>

// ---------------------------------------------------------------------------
// Problem constants
// ---------------------------------------------------------------------------
constexpr int BATCH   = 2;
constexpr int SEQ     = 2048;
constexpr int DMODEL  = 2048;
constexpr int DFF     = 8192;
constexpr int NHEADS  = 16;
constexpr int NKV     = 8;
constexpr int HD      = 128;
constexpr int DKV     = NKV * HD;      // 1024
constexpr int TOK     = BATCH * SEQ;   // 4096
constexpr float EPSV  = 1e-5f;
constexpr float SM_SCALE = 0.08838834764831845f; // 128^-0.5

// ---------------------------------------------------------------------------
// Scratch (device globals; allocation in kernel_launch is forbidden)
// ---------------------------------------------------------------------------
__device__ float g_x1   [(size_t)TOK * DMODEL];
__device__ float g_q    [(size_t)TOK * DMODEL];
__device__ float g_k    [(size_t)TOK * DKV];
__device__ float g_v    [(size_t)TOK * DKV];
__device__ float g_scores[(size_t)BATCH * NHEADS * SEQ * SEQ]; // 536 MB
__device__ float g_ctx  [(size_t)TOK * DMODEL];
__device__ float g_h2   [(size_t)TOK * DMODEL];
__device__ float g_x2   [(size_t)TOK * DMODEL];
__device__ float g_gate [(size_t)TOK * DFF];
__device__ float g_up   [(size_t)TOK * DFF];

// ---------------------------------------------------------------------------
// Tiled SGEMM body: C[M,N] = A * op(B) (+ R), fp32.
//  NN: B is [K,N] row-major.  NT: B is [N,K] row-major (C = A * B^T).
//  Tile: 128x128x16, 256 threads, 8x8 per-thread micro-tile (split 4+4 so
//  operand fetches are contiguous float4 -> conflict-free LDS.128).
//  All dims assumed divisible by tile sizes (true for every call here).
// ---------------------------------------------------------------------------
constexpr int BM = 128, BN = 128, BK = 16;

template <bool NT>
__device__ __forceinline__ void gemm_body(
    const float* __restrict__ A, const float* __restrict__ B,
    const float* __restrict__ R, float* __restrict__ C,
    int K, int lda, int ldb, int ldc)
{
    __shared__ float As[BK][BM];
    __shared__ float Bs[BK][BN];

    const int tid = threadIdx.x;
    const int tx  = tid & 15;        // 0..15 -> N
    const int ty  = tid >> 4;        // 0..15 -> M
    const int m0  = blockIdx.y * BM;
    const int n0  = blockIdx.x * BN;

    float acc[8][8];
    #pragma unroll
    for (int i = 0; i < 8; i++)
        #pragma unroll
        for (int j = 0; j < 8; j++) acc[i][j] = 0.f;

    for (int k0 = 0; k0 < K; k0 += BK) {
        // ---- load A tile [BM x BK], store transposed As[k][m]
        #pragma unroll
        for (int it = 0; it < 2; it++) {
            int s   = tid + it * 256;          // 0..511
            int row = s >> 2;                  // 0..127
            int kc  = (s & 3) << 2;            // 0,4,8,12
            float4 v = *reinterpret_cast<const float4*>(
                A + (long)(m0 + row) * lda + k0 + kc);
            As[kc + 0][row] = v.x;
            As[kc + 1][row] = v.y;
            As[kc + 2][row] = v.z;
            As[kc + 3][row] = v.w;
        }
        // ---- load B tile -> Bs[k][n]
        if (NT) {
            // B is [N,K]: load rows of B, transpose into Bs
            #pragma unroll
            for (int it = 0; it < 2; it++) {
                int s    = tid + it * 256;
                int nrow = s >> 2;             // 0..127
                int kc   = (s & 3) << 2;
                float4 v = *reinterpret_cast<const float4*>(
                    B + (long)(n0 + nrow) * ldb + k0 + kc);
                Bs[kc + 0][nrow] = v.x;
                Bs[kc + 1][nrow] = v.y;
                Bs[kc + 2][nrow] = v.z;
                Bs[kc + 3][nrow] = v.w;
            }
        } else {
            #pragma unroll
            for (int it = 0; it < 2; it++) {
                int s  = tid + it * 256;
                int kr = s >> 5;               // 0..15
                int nc = (s & 31) << 2;        // 0..124
                *reinterpret_cast<float4*>(&Bs[kr][nc]) =
                    *reinterpret_cast<const float4*>(
                        B + (long)(k0 + kr) * ldb + n0 + nc);
            }
        }
        __syncthreads();

        #pragma unroll
        for (int kk = 0; kk < BK; kk++) {
            float4 a0 = *reinterpret_cast<const float4*>(&As[kk][ty * 4]);
            float4 a1 = *reinterpret_cast<const float4*>(&As[kk][64 + ty * 4]);
            float4 b0 = *reinterpret_cast<const float4*>(&Bs[kk][tx * 4]);
            float4 b1 = *reinterpret_cast<const float4*>(&Bs[kk][64 + tx * 4]);
            float a[8] = {a0.x, a0.y, a0.z, a0.w, a1.x, a1.y, a1.z, a1.w};
            float b[8] = {b0.x, b0.y, b0.z, b0.w, b1.x, b1.y, b1.z, b1.w};
            #pragma unroll
            for (int i = 0; i < 8; i++)
                #pragma unroll
                for (int j = 0; j < 8; j++)
                    acc[i][j] = fmaf(a[i], b[j], acc[i][j]);
        }
        __syncthreads();
    }

    // ---- epilogue (optional residual add), float4 stores
    #pragma unroll
    for (int half = 0; half < 2; half++) {
        #pragma unroll
        for (int i = 0; i < 4; i++) {
            int row = m0 + half * 64 + ty * 4 + i;
            float* cp = C + (long)row * ldc + n0;
            float4 r0, r1;
            int ai = half * 4 + i;
            r0.x = acc[ai][0]; r0.y = acc[ai][1]; r0.z = acc[ai][2]; r0.w = acc[ai][3];
            r1.x = acc[ai][4]; r1.y = acc[ai][5]; r1.z = acc[ai][6]; r1.w = acc[ai][7];
            if (R) {
                const float* rp = R + (long)row * ldc + n0;
                float4 q0 = *reinterpret_cast<const float4*>(rp + tx * 4);
                float4 q1 = *reinterpret_cast<const float4*>(rp + 64 + tx * 4);
                r0.x += q0.x; r0.y += q0.y; r0.z += q0.z; r0.w += q0.w;
                r1.x += q1.x; r1.y += q1.y; r1.z += q1.z; r1.w += q1.w;
            }
            *reinterpret_cast<float4*>(cp + tx * 4)      = r0;
            *reinterpret_cast<float4*>(cp + 64 + tx * 4) = r1;
        }
    }
}

__global__ __launch_bounds__(256, 2) void sgemm_nn_kernel(
    const float* __restrict__ A, const float* __restrict__ B,
    const float* __restrict__ R, float* __restrict__ C,
    int K, int lda, int ldb, int ldc)
{
    gemm_body<false>(A, B, R, C, K, lda, ldb, ldc);
}

// scores[z=(b*16+h)][q][k] = Q_bh[q,:] . K_b(h/2)[k,:]   (scale applied in softmax)
__global__ __launch_bounds__(256, 2) void scores_gemm_kernel()
{
    int z  = blockIdx.z;
    int b  = z >> 4;
    int h  = z & 15;
    int kh = h >> 1;
    const float* A  = g_q + (long)b * SEQ * DMODEL + h * HD;
    const float* Bp = g_k + (long)b * SEQ * DKV + kh * HD;
    float*       Cp = g_scores + (long)z * SEQ * SEQ;
    gemm_body<true>(A, Bp, nullptr, Cp, HD, DMODEL, DKV, SEQ);
}

// ctx[b,s, h*128+d] = sum_k P_bh[s,k] * V_b(h/2)[k,d]
__global__ __launch_bounds__(256, 2) void pv_gemm_kernel()
{
    int z  = blockIdx.z;
    int b  = z >> 4;
    int h  = z & 15;
    int kh = h >> 1;
    const float* A  = g_scores + (long)z * SEQ * SEQ;
    const float* Bp = g_v + (long)b * SEQ * DKV + kh * HD;
    float*       Cp = g_ctx + (long)b * SEQ * DMODEL + h * HD;
    gemm_body<false>(A, Bp, nullptr, Cp, SEQ, SEQ, DKV, DMODEL);
}

// ---------------------------------------------------------------------------
// RMSNorm: one block per row (D=2048), 256 threads x 8 elems
// ---------------------------------------------------------------------------
__device__ __forceinline__ float block_reduce_sum(float v)
{
    __shared__ float red[32];
    int lid = threadIdx.x & 31, wid = threadIdx.x >> 5;
    #pragma unroll
    for (int o = 16; o; o >>= 1) v += __shfl_xor_sync(0xffffffffu, v, o);
    if (lid == 0) red[wid] = v;
    __syncthreads();
    v = (threadIdx.x < (blockDim.x >> 5)) ? red[threadIdx.x] : 0.f;
    if (wid == 0) {
        #pragma unroll
        for (int o = 16; o; o >>= 1) v += __shfl_xor_sync(0xffffffffu, v, o);
        if (lid == 0) red[0] = v;
    }
    __syncthreads();
    return red[0];
}

__device__ __forceinline__ float block_reduce_max(float v)
{
    __shared__ float red[32];
    int lid = threadIdx.x & 31, wid = threadIdx.x >> 5;
    #pragma unroll
    for (int o = 16; o; o >>= 1) v = fmaxf(v, __shfl_xor_sync(0xffffffffu, v, o));
    if (lid == 0) red[wid] = v;
    __syncthreads();
    v = (threadIdx.x < (blockDim.x >> 5)) ? red[threadIdx.x] : -INFINITY;
    if (wid == 0) {
        #pragma unroll
        for (int o = 16; o; o >>= 1) v = fmaxf(v, __shfl_xor_sync(0xffffffffu, v, o));
        if (lid == 0) red[0] = v;
    }
    __syncthreads();
    return red[0];
}

__global__ __launch_bounds__(256) void rmsnorm_kernel(
    const float* __restrict__ x, const float* __restrict__ w,
    float* __restrict__ out)
{
    long row = blockIdx.x;
    const float* xr = x + row * DMODEL;
    float* outr = out + row * DMODEL;
    float vals[8];
    float ss = 0.f;
    #pragma unroll
    for (int i = 0; i < 8; i++) {
        int idx = threadIdx.x + i * 256;
        vals[i] = xr[idx];
        ss = fmaf(vals[i], vals[i], ss);
    }
    float total = block_reduce_sum(ss);
    float rstd = rsqrtf(total * (1.0f / DMODEL) + EPSV);
    #pragma unroll
    for (int i = 0; i < 8; i++) {
        int idx = threadIdx.x + i * 256;
        outr[idx] = vals[i] * rstd * w[idx];
    }
}

// ---------------------------------------------------------------------------
// RoPE (in-place, HF style): out[j] = e*c - o*s ; out[64+j] = e*s + o*c
// where e = x[2j], o = x[2j+1]. One 64-thread block per (token, head).
// ---------------------------------------------------------------------------
__global__ __launch_bounds__(64) void rotary_kernel(
    float* __restrict__ x, const float* __restrict__ cs,
    const float* __restrict__ sn, int ld)
{
    long base = (long)blockIdx.x * ld + blockIdx.y * HD;
    int j = threadIdx.x;                    // 0..63
    float e = x[base + 2 * j];
    float o = x[base + 2 * j + 1];
    float c = cs[(long)blockIdx.x * 64 + j];
    float s = sn[(long)blockIdx.x * 64 + j];
    __syncthreads();                        // all reads before any write
    x[base + j]      = e * c - o * s;
    x[base + 64 + j] = e * s + o * c;
}

// ---------------------------------------------------------------------------
// Softmax over score rows (applies scale and additive mask), single pass.
// grid = (SEQ, B*H), block = 256, each thread owns 8 elems in registers.
// ---------------------------------------------------------------------------
__global__ __launch_bounds__(256) void softmax_kernel(const float* __restrict__ mask)
{
    int z = blockIdx.y;
    int b = z >> 4;
    long row = blockIdx.x;
    float* srow = g_scores + ((long)z * SEQ + row) * SEQ;
    const float* mrow = mask + ((long)b * SEQ + row) * SEQ;

    float v[8];
    float mx = -INFINITY;
    #pragma unroll
    for (int i = 0; i < 8; i++) {
        int idx = threadIdx.x + i * 256;
        v[i] = fmaf(srow[idx], SM_SCALE, mrow[idx]);
        mx = fmaxf(mx, v[i]);
    }
    float bm = block_reduce_max(mx);
    float sum = 0.f;
    #pragma unroll
    for (int i = 0; i < 8; i++) {
        v[i] = expf(v[i] - bm);
        sum += v[i];
    }
    float total = block_reduce_sum(sum);
    float inv = 1.0f / total;
    #pragma unroll
    for (int i = 0; i < 8; i++) {
        int idx = threadIdx.x + i * 256;
        srow[idx] = v[i] * inv;
    }
}

// ---------------------------------------------------------------------------
// SwiGLU gate: gate <- silu(gate) * up
// ---------------------------------------------------------------------------
__global__ __launch_bounds__(256) void silu_mul_kernel(long n)
{
    long i = (long)blockIdx.x * blockDim.x + threadIdx.x;
    if (i < n) {
        float g = g_gate[i];
        float u = g_up[i];
        g_gate[i] = u * g / (1.0f + expf(-g));
    }
}

// ---------------------------------------------------------------------------
// Launch
// ---------------------------------------------------------------------------
extern "C" void kernel_launch(void* const* d_in, const int* in_sizes, int n_in,
                              void* d_out, int out_size)
{
    const float* hs   = (const float*)d_in[0];
    const float* cosp = (const float*)d_in[1];
    const float* sinp = (const float*)d_in[2];
    const float* mask = (const float*)d_in[3];
    const float* wq   = (const float*)d_in[4];
    const float* wk   = (const float*)d_in[5];
    const float* wv   = (const float*)d_in[6];
    const float* wo   = (const float*)d_in[7];
    const float* wg   = (const float*)d_in[8];
    const float* wu   = (const float*)d_in[9];
    const float* wd   = (const float*)d_in[10];
    const float* ln1  = (const float*)d_in[11];
    const float* ln2  = (const float*)d_in[12];
    float* out = (float*)d_out;

    float *x1, *q, *k, *v, *ctx, *h2, *x2, *gate, *up;
    cudaGetSymbolAddress((void**)&x1,   g_x1);
    cudaGetSymbolAddress((void**)&q,    g_q);
    cudaGetSymbolAddress((void**)&k,    g_k);
    cudaGetSymbolAddress((void**)&v,    g_v);
    cudaGetSymbolAddress((void**)&ctx,  g_ctx);
    cudaGetSymbolAddress((void**)&h2,   g_h2);
    cudaGetSymbolAddress((void**)&x2,   g_x2);
    cudaGetSymbolAddress((void**)&gate, g_gate);
    cudaGetSymbolAddress((void**)&up,   g_up);

    // 1) x1 = rmsnorm(h, ln1)
    rmsnorm_kernel<<<TOK, 256>>>(hs, ln1, x1);

    // 2) q/k/v projections
    sgemm_nn_kernel<<<dim3(DMODEL / BN, TOK / BM), 256>>>(x1, wq, nullptr, q,
        DMODEL, DMODEL, DMODEL, DMODEL);
    sgemm_nn_kernel<<<dim3(DKV / BN, TOK / BM), 256>>>(x1, wk, nullptr, k,
        DMODEL, DMODEL, DKV, DKV);
    sgemm_nn_kernel<<<dim3(DKV / BN, TOK / BM), 256>>>(x1, wv, nullptr, v,
        DMODEL, DMODEL, DKV, DKV);

    // 3) RoPE on q and k
    rotary_kernel<<<dim3(TOK, NHEADS), 64>>>(q, cosp, sinp, DMODEL);
    rotary_kernel<<<dim3(TOK, NKV),    64>>>(k, cosp, sinp, DKV);

    // 4) scores = Q K^T  (batched over b,h)
    scores_gemm_kernel<<<dim3(SEQ / BN, SEQ / BM, BATCH * NHEADS), 256>>>();

    // 5) softmax (scale + mask folded in)
    softmax_kernel<<<dim3(SEQ, BATCH * NHEADS), 256>>>(mask);

    // 6) ctx = P @ V  (writes [b,s,h,d] layout)
    pv_gemm_kernel<<<dim3(1, SEQ / BM, BATCH * NHEADS), 256>>>();

    // 7) h2 = hs + ctx @ wo
    sgemm_nn_kernel<<<dim3(DMODEL / BN, TOK / BM), 256>>>(ctx, wo, hs, h2,
        DMODEL, DMODEL, DMODEL, DMODEL);

    // 8) x2 = rmsnorm(h2, ln2)
    rmsnorm_kernel<<<TOK, 256>>>(h2, ln2, x2);

    // 9) MLP
    sgemm_nn_kernel<<<dim3(DFF / BN, TOK / BM), 256>>>(x2, wg, nullptr, gate,
        DMODEL, DMODEL, DFF, DFF);
    sgemm_nn_kernel<<<dim3(DFF / BN, TOK / BM), 256>>>(x2, wu, nullptr, up,
        DMODEL, DMODEL, DFF, DFF);

    long n = (long)TOK * DFF;
    silu_mul_kernel<<<(unsigned)((n + 255) / 256), 256>>>(n);

    // 10) out = h2 + (silu(gate)*up) @ wd
    sgemm_nn_kernel<<<dim3(DMODEL / BN, TOK / BM), 256>>>(gate, wd, h2, out,
        DFF, DFF, DMODEL, DMODEL);
}

// round 4
// speedup vs baseline: 2.5768x; 2.5757x over previous
#include <cuda_runtime.h>
#include <cuda_bf16.h>
#include <math.h>
#include <stdint.h>

// ---------------------------------------------------------------------------
// Problem constants
// ---------------------------------------------------------------------------
constexpr int BATCH   = 2;
constexpr int SEQ     = 2048;
constexpr int DMODEL  = 2048;
constexpr int DFF     = 8192;
constexpr int NHEADS  = 16;
constexpr int NKV     = 8;
constexpr int HD      = 128;
constexpr int DKV     = NKV * HD;      // 1024
constexpr int TOK     = BATCH * SEQ;   // 4096
constexpr float EPSV  = 1e-5f;
constexpr float SM_SCALE = 0.08838834764831845f; // 128^-0.5

typedef __nv_bfloat16 bf16;

// ---------------------------------------------------------------------------
// Scratch (device globals; allocation anywhere is forbidden)
// ---------------------------------------------------------------------------
__device__ bf16  g_x1h [(size_t)TOK * DMODEL];
__device__ float g_q   [(size_t)TOK * DMODEL];
__device__ float g_k   [(size_t)TOK * DKV];
__device__ float g_v   [(size_t)TOK * DKV];
__device__ bf16  g_qh  [(size_t)TOK * DMODEL];
__device__ bf16  g_kh  [(size_t)TOK * DKV];
__device__ bf16  g_vth [(size_t)TOK * DKV];   // V^T: [(b*8+kh)][128][SEQ]
__device__ float g_scores[(size_t)BATCH * NHEADS * SEQ * SEQ]; // 536 MB
__device__ bf16  g_ph  [(size_t)BATCH * NHEADS * SEQ * SEQ];
__device__ float g_ctx [(size_t)TOK * DMODEL];
__device__ bf16  g_ctxh[(size_t)TOK * DMODEL];
__device__ float g_h2  [(size_t)TOK * DMODEL];
__device__ bf16  g_x2h [(size_t)TOK * DMODEL];
__device__ bf16  g_x2l [(size_t)TOK * DMODEL];
__device__ float g_gate[(size_t)TOK * DFF];
__device__ float g_up  [(size_t)TOK * DFF];
__device__ bf16  g_mh  [(size_t)TOK * DFF];
__device__ bf16  g_ml  [(size_t)TOK * DFF];
// transposed-converted weights: [N, K]
__device__ bf16  g_wqt_h[(size_t)DMODEL * DMODEL];
__device__ bf16  g_wkt_h[(size_t)DKV * DMODEL];
__device__ bf16  g_wvt_h[(size_t)DKV * DMODEL];
__device__ bf16  g_wot_h[(size_t)DMODEL * DMODEL];
__device__ bf16  g_wgt_h[(size_t)DFF * DMODEL];
__device__ bf16  g_wgt_l[(size_t)DFF * DMODEL];
__device__ bf16  g_wut_h[(size_t)DFF * DMODEL];
__device__ bf16  g_wut_l[(size_t)DFF * DMODEL];
__device__ bf16  g_wdt_h[(size_t)DMODEL * DFF];
__device__ bf16  g_wdt_l[(size_t)DMODEL * DFF];

// ---------------------------------------------------------------------------
// PTX helpers — only baseline sm_80+ features (harness compiles plain sm_103,
// so no tcgen05/TMEM; tensor pipe reached via legacy HMMA mma.sync).
// ---------------------------------------------------------------------------
__device__ __forceinline__ uint32_t smem_u32(const void* p) {
    uint32_t a;
    asm("{ .reg .u64 t; cvta.to.shared.u64 t, %1; cvt.u32.u64 %0, t; }"
        : "=r"(a) : "l"(p));
    return a;
}

__device__ __forceinline__ void cp16(uint32_t saddr, const void* g) {
    unsigned long long ga = (unsigned long long)__cvta_generic_to_global(g);
    asm volatile("cp.async.cg.shared.global [%0], [%1], 16;\n"
                 :: "r"(saddr), "l"(ga));
}
#define CP_COMMIT() asm volatile("cp.async.commit_group;\n" ::: "memory")
#define CP_WAIT1()  asm volatile("cp.async.wait_group 1;\n" ::: "memory")

__device__ __forceinline__ void ldmx4(uint32_t* r, uint32_t addr) {
    asm volatile("ldmatrix.sync.aligned.m8n8.x4.shared.b16 {%0,%1,%2,%3}, [%4];\n"
        : "=r"(r[0]), "=r"(r[1]), "=r"(r[2]), "=r"(r[3]) : "r"(addr));
}

__device__ __forceinline__ void mma16816(float* c, const uint32_t* a, const uint32_t* b) {
    asm volatile(
        "mma.sync.aligned.m16n8k16.row.col.f32.bf16.bf16.f32 "
        "{%0,%1,%2,%3}, {%4,%5,%6,%7}, {%8,%9}, {%0,%1,%2,%3};\n"
        : "+f"(c[0]), "+f"(c[1]), "+f"(c[2]), "+f"(c[3])
        : "r"(a[0]), "r"(a[1]), "r"(a[2]), "r"(a[3]), "r"(b[0]), "r"(b[1]));
}

__device__ __forceinline__ void split2(float v, bf16& h, bf16& l) {
    h = __float2bfloat16(v);
    l = __float2bfloat16(v - __bfloat162float(h));
}

// ---------------------------------------------------------------------------
// MMA GEMM: C[128 x 128] tile of A[M,K] * Bt[N,K]^T (+ R), fp32 out.
// NT=1: plain bf16. NT=3: 3-term hi/lo split (~fp32 accuracy).
// K % 32 == 0. smem rows: 32 bf16 = 64B padded to 80B (ldmatrix conflict-free).
// ---------------------------------------------------------------------------
constexpr int LDSS = 80;                 // smem row stride bytes
constexpr int MATB = 128 * LDSS;         // 10240 B per matrix tile per stage

template <int NT>
__device__ __forceinline__ void load_stage(
    uint32_t sb, int s, const bf16* __restrict__ Ah, const bf16* __restrict__ Al,
    const bf16* __restrict__ Bh, const bf16* __restrict__ Bl,
    long lda, long ldb, int k0, int tid)
{
    constexpr int STAGE = (NT == 3 ? 4 : 2) * MATB;
    uint32_t base = sb + (uint32_t)(s * STAGE);
    #pragma unroll
    for (int i = 0; i < 2; i++) {
        int idx = tid + i * 256;
        int r = idx >> 2, cb = (idx & 3) << 4;   // row, k-byte offset
        uint32_t so = (uint32_t)(r * LDSS + cb);
        long ga = (long)r * lda + k0 + (cb >> 1);
        long gb = (long)r * ldb + k0 + (cb >> 1);
        cp16(base + so, Ah + ga);
        if (NT == 3) cp16(base + MATB + so, Al + ga);
        cp16(base + (NT == 3 ? 2 : 1) * MATB + so, Bh + gb);
        if (NT == 3) cp16(base + 3 * MATB + so, Bl + gb);
    }
}

template <int NT>
__device__ __forceinline__ void compute_stage(
    uint32_t sb, int s, int wm, int wn, int l, float acc[4][4][4])
{
    constexpr int STAGE = (NT == 3 ? 4 : 2) * MATB;
    uint32_t As  = sb + (uint32_t)(s * STAGE);
    uint32_t Als = As + MATB;
    uint32_t Bs  = As + (NT == 3 ? 2 : 1) * MATB;
    uint32_t Bls = Bs + MATB;
    uint32_t a_off = (uint32_t)((wm * 64 + (l & 15)) * LDSS + ((l >> 4) << 4));
    uint32_t b_off = (uint32_t)((wn * 32 + ((l >> 4) << 3) + (l & 7)) * LDSS
                                + (((l >> 3) & 1) << 4));
    #pragma unroll
    for (int kk = 0; kk < 2; kk++) {
        uint32_t kb = (uint32_t)(kk * 32);   // 16 elems = 32 B
        uint32_t ah[4][4], bh[4][2];
        uint32_t al[4][4], bl[4][2];
        #pragma unroll
        for (int m = 0; m < 4; m++)
            ldmx4(ah[m], As + a_off + m * (16 * LDSS) + kb);
        #pragma unroll
        for (int p = 0; p < 2; p++) {
            uint32_t r[4];
            ldmx4(r, Bs + b_off + p * (16 * LDSS) + kb);
            bh[2*p][0] = r[0]; bh[2*p][1] = r[1];
            bh[2*p+1][0] = r[2]; bh[2*p+1][1] = r[3];
        }
        if (NT == 3) {
            #pragma unroll
            for (int m = 0; m < 4; m++)
                ldmx4(al[m], Als + a_off + m * (16 * LDSS) + kb);
            #pragma unroll
            for (int p = 0; p < 2; p++) {
                uint32_t r[4];
                ldmx4(r, Bls + b_off + p * (16 * LDSS) + kb);
                bl[2*p][0] = r[0]; bl[2*p][1] = r[1];
                bl[2*p+1][0] = r[2]; bl[2*p+1][1] = r[3];
            }
        }
        #pragma unroll
        for (int m = 0; m < 4; m++)
            #pragma unroll
            for (int n = 0; n < 4; n++) {
                mma16816(acc[m][n], ah[m], bh[n]);
                if (NT == 3) {
                    mma16816(acc[m][n], ah[m], bl[n]);
                    mma16816(acc[m][n], al[m], bh[n]);
                }
            }
    }
}

template <int NT>
__device__ __forceinline__ void gemm_mma(
    const bf16* __restrict__ a_hi, const bf16* __restrict__ a_lo, long lda,
    const bf16* __restrict__ b_hi, const bf16* __restrict__ b_lo, long ldb,
    const float* __restrict__ R, float* __restrict__ C, long ldc,
    int K, int m0, int n0)
{
    extern __shared__ char smem[];
    uint32_t sb = smem_u32(smem);
    const int tid = threadIdx.x, wid = tid >> 5, l = tid & 31;
    const int wm = wid & 1, wn = wid >> 1;

    const bf16* Ah = a_hi + (long)m0 * lda;
    const bf16* Al = (NT == 3) ? a_lo + (long)m0 * lda : Ah;
    const bf16* Bh = b_hi + (long)n0 * ldb;
    const bf16* Bl = (NT == 3) ? b_lo + (long)n0 * ldb : Bh;

    float acc[4][4][4];
    #pragma unroll
    for (int m = 0; m < 4; m++)
        #pragma unroll
        for (int n = 0; n < 4; n++)
            #pragma unroll
            for (int i = 0; i < 4; i++) acc[m][n][i] = 0.f;

    const int nk = K >> 5;
    load_stage<NT>(sb, 0, Ah, Al, Bh, Bl, lda, ldb, 0, tid);
    CP_COMMIT();
    for (int c = 0; c < nk; c++) {
        if (c + 1 < nk)
            load_stage<NT>(sb, (c + 1) & 1, Ah, Al, Bh, Bl, lda, ldb,
                           (c + 1) * 32, tid);
        CP_COMMIT();
        CP_WAIT1();
        __syncthreads();
        compute_stage<NT>(sb, c & 1, wm, wn, l, acc);
        __syncthreads();
    }

    // epilogue (optional residual add)
    const int row0 = m0 + wm * 64, col0 = n0 + wn * 32;
    #pragma unroll
    for (int m = 0; m < 4; m++) {
        int r0 = row0 + m * 16 + (l >> 2);
        #pragma unroll
        for (int n = 0; n < 4; n++) {
            int cc = col0 + n * 8 + (l & 3) * 2;
            float2 v0 = make_float2(acc[m][n][0], acc[m][n][1]);
            float2 v1 = make_float2(acc[m][n][2], acc[m][n][3]);
            if (R) {
                float2 q0 = *(const float2*)(R + (long)r0 * ldc + cc);
                float2 q1 = *(const float2*)(R + (long)(r0 + 8) * ldc + cc);
                v0.x += q0.x; v0.y += q0.y; v1.x += q1.x; v1.y += q1.y;
            }
            *(float2*)(C + (long)r0 * ldc + cc)       = v0;
            *(float2*)(C + (long)(r0 + 8) * ldc + cc) = v1;
        }
    }
}

constexpr int SM1 = 2 * 2 * MATB;   // 40960
constexpr int SM3 = 2 * 4 * MATB;   // 81920

// ---------------------------------------------------------------------------
// GEMM wrapper kernels
// ---------------------------------------------------------------------------
__global__ __launch_bounds__(256) void mma_gemm1_kernel(
    const bf16* a, long lda, const bf16* b, long ldb,
    const float* R, float* C, long ldc, int K)
{
    gemm_mma<1>(a, nullptr, lda, b, nullptr, ldb, R, C, ldc, K,
                blockIdx.y * 128, blockIdx.x * 128);
}

__global__ __launch_bounds__(256) void mma_gemm3_kernel(
    const bf16* ah, const bf16* al, long lda,
    const bf16* bh, const bf16* bl, long ldb,
    const float* R, float* C, long ldc, int K)
{
    gemm_mma<3>(ah, al, lda, bh, bl, ldb, R, C, ldc, K,
                blockIdx.y * 128, blockIdx.x * 128);
}

__global__ __launch_bounds__(256) void mma_scores_kernel()
{
    int z = blockIdx.z, b = z >> 4, h = z & 15, kh = h >> 1;
    const bf16* A = g_qh + (long)b * SEQ * DMODEL + h * HD;
    const bf16* B = g_kh + (long)b * SEQ * DKV + kh * HD;
    float* C = g_scores + (long)z * SEQ * SEQ;
    gemm_mma<1>(A, nullptr, DMODEL, B, nullptr, DKV, nullptr, C, SEQ, HD,
                blockIdx.y * 128, blockIdx.x * 128);
}

__global__ __launch_bounds__(256) void mma_pv_kernel()
{
    int z = blockIdx.z, b = z >> 4, h = z & 15, kh = h >> 1;
    const bf16* A = g_ph + (long)z * SEQ * SEQ;
    const bf16* B = g_vth + (long)(b * NKV + kh) * HD * SEQ;
    float* C = g_ctx + (long)b * SEQ * DMODEL + h * HD;
    gemm_mma<1>(A, nullptr, SEQ, B, nullptr, SEQ, nullptr, C, DMODEL, SEQ,
                blockIdx.y * 128, 0);
}

// ---------------------------------------------------------------------------
// Reductions
// ---------------------------------------------------------------------------
__device__ __forceinline__ float block_reduce_sum(float v)
{
    __shared__ float red[32];
    int lid = threadIdx.x & 31, wid = threadIdx.x >> 5;
    #pragma unroll
    for (int o = 16; o; o >>= 1) v += __shfl_xor_sync(0xffffffffu, v, o);
    if (lid == 0) red[wid] = v;
    __syncthreads();
    v = (threadIdx.x < 8) ? red[threadIdx.x] : 0.f;
    if (wid == 0) {
        #pragma unroll
        for (int o = 4; o; o >>= 1) v += __shfl_xor_sync(0xffffffffu, v, o);
        if (lid == 0) red[0] = v;
    }
    __syncthreads();
    return red[0];
}
__device__ __forceinline__ float block_reduce_max(float v)
{
    __shared__ float red[32];
    int lid = threadIdx.x & 31, wid = threadIdx.x >> 5;
    #pragma unroll
    for (int o = 16; o; o >>= 1) v = fmaxf(v, __shfl_xor_sync(0xffffffffu, v, o));
    if (lid == 0) red[wid] = v;
    __syncthreads();
    v = (threadIdx.x < 8) ? red[threadIdx.x] : -INFINITY;
    if (wid == 0) {
        #pragma unroll
        for (int o = 4; o; o >>= 1) v = fmaxf(v, __shfl_xor_sync(0xffffffffu, v, o));
        if (lid == 0) red[0] = v;
    }
    __syncthreads();
    return red[0];
}

// ---------------------------------------------------------------------------
// RMSNorm -> bf16 hi (+ optional lo)
// ---------------------------------------------------------------------------
__global__ __launch_bounds__(256) void rmsnorm_split_kernel(
    const float* __restrict__ x, const float* __restrict__ w,
    bf16* __restrict__ oh, bf16* __restrict__ ol)
{
    long row = blockIdx.x;
    const float* xr = x + row * DMODEL;
    float vals[8];
    float ss = 0.f;
    #pragma unroll
    for (int i = 0; i < 8; i++) {
        int idx = threadIdx.x + i * 256;
        vals[i] = xr[idx];
        ss = fmaf(vals[i], vals[i], ss);
    }
    float total = block_reduce_sum(ss);
    float rstd = rsqrtf(total * (1.0f / DMODEL) + EPSV);
    #pragma unroll
    for (int i = 0; i < 8; i++) {
        int idx = threadIdx.x + i * 256;
        float v = vals[i] * rstd * w[idx];
        bf16 h, l; split2(v, h, l);
        oh[row * DMODEL + idx] = h;
        if (ol) ol[row * DMODEL + idx] = l;
    }
}

// ---------------------------------------------------------------------------
// RoPE (HF-style) fp32 -> bf16 hi
// ---------------------------------------------------------------------------
__global__ __launch_bounds__(64) void rope_kernel(
    const float* __restrict__ x, const float* __restrict__ cs,
    const float* __restrict__ sn, bf16* __restrict__ oh, int ld)
{
    long base = (long)blockIdx.x * ld + blockIdx.y * HD;
    int j = threadIdx.x;
    float e = x[base + 2 * j];
    float o = x[base + 2 * j + 1];
    float c = cs[(long)blockIdx.x * 64 + j];
    float s = sn[(long)blockIdx.x * 64 + j];
    oh[base + j]      = __float2bfloat16(e * c - o * s);
    oh[base + 64 + j] = __float2bfloat16(e * s + o * c);
}

// ---------------------------------------------------------------------------
// Weight transpose + split: in [RI, CI] fp32 -> out [CI, RI] bf16 hi (+lo)
// ---------------------------------------------------------------------------
__global__ __launch_bounds__(256) void transpose_split_kernel(
    const float* __restrict__ in, bf16* __restrict__ oh, bf16* __restrict__ ol,
    int RI, int CI)
{
    __shared__ float t[32][33];
    int tx = threadIdx.x & 31, ty = threadIdx.x >> 5;
    int r0 = blockIdx.y * 32, c0 = blockIdx.x * 32;
    #pragma unroll
    for (int i = 0; i < 4; i++)
        t[ty + i * 8][tx] = in[(long)(r0 + ty + i * 8) * CI + c0 + tx];
    __syncthreads();
    #pragma unroll
    for (int i = 0; i < 4; i++) {
        float v = t[tx][ty + i * 8];
        long o = (long)(c0 + ty + i * 8) * RI + r0 + tx;
        bf16 h, l; split2(v, h, l);
        oh[o] = h;
        if (ol) ol[o] = l;
    }
}

// V transpose: g_v [b, s, kh*128+d] -> g_vth [(b*8+kh)][d][s] bf16
__global__ __launch_bounds__(256) void vT_kernel()
{
    __shared__ float t[32][33];
    int z = blockIdx.z;
    int b = z >> 3, kh = z & 7;
    const float* in = g_v + (long)b * SEQ * DKV + kh * HD;
    bf16* oh = g_vth + (long)z * HD * SEQ;
    int tx = threadIdx.x & 31, ty = threadIdx.x >> 5;
    int s0 = blockIdx.y * 32, d0 = blockIdx.x * 32;
    #pragma unroll
    for (int i = 0; i < 4; i++)
        t[ty + i * 8][tx] = in[(long)(s0 + ty + i * 8) * DKV + d0 + tx];
    __syncthreads();
    #pragma unroll
    for (int i = 0; i < 4; i++)
        oh[(long)(d0 + ty + i * 8) * SEQ + s0 + tx] =
            __float2bfloat16(t[tx][ty + i * 8]);
}

// ---------------------------------------------------------------------------
// Softmax (scale + mask) -> bf16
// ---------------------------------------------------------------------------
__global__ __launch_bounds__(256) void softmax_kernel(const float* __restrict__ mask)
{
    int z = blockIdx.y;
    int b = z >> 4;
    long row = blockIdx.x;
    const float* srow = g_scores + ((long)z * SEQ + row) * SEQ;
    const float* mrow = mask + ((long)b * SEQ + row) * SEQ;
    bf16* phr = g_ph + ((long)z * SEQ + row) * SEQ;

    float v[8];
    float mx = -INFINITY;
    #pragma unroll
    for (int i = 0; i < 8; i++) {
        int idx = threadIdx.x + i * 256;
        v[i] = fmaf(srow[idx], SM_SCALE, mrow[idx]);
        mx = fmaxf(mx, v[i]);
    }
    float bm = block_reduce_max(mx);
    float sum = 0.f;
    #pragma unroll
    for (int i = 0; i < 8; i++) {
        v[i] = expf(v[i] - bm);
        sum += v[i];
    }
    float total = block_reduce_sum(sum);
    float inv = 1.0f / total;
    #pragma unroll
    for (int i = 0; i < 8; i++) {
        int idx = threadIdx.x + i * 256;
        phr[idx] = __float2bfloat16(v[i] * inv);
    }
}

// ---------------------------------------------------------------------------
// Elementwise converts
// ---------------------------------------------------------------------------
__global__ __launch_bounds__(256) void ctx_cvt_kernel()
{
    long i = (long)blockIdx.x * 256 + threadIdx.x;
    g_ctxh[i] = __float2bfloat16(g_ctx[i]);
}

__global__ __launch_bounds__(256) void silu_split_kernel()
{
    long i = (long)blockIdx.x * 256 + threadIdx.x;
    float g = g_gate[i], u = g_up[i];
    float v = u * g / (1.0f + expf(-g));
    bf16 h, l; split2(v, h, l);
    g_mh[i] = h; g_ml[i] = l;
}

// ---------------------------------------------------------------------------
// Launch
// ---------------------------------------------------------------------------
extern "C" void kernel_launch(void* const* d_in, const int* in_sizes, int n_in,
                              void* d_out, int out_size)
{
    const float* hs   = (const float*)d_in[0];
    const float* cosp = (const float*)d_in[1];
    const float* sinp = (const float*)d_in[2];
    const float* mask = (const float*)d_in[3];
    const float* wq   = (const float*)d_in[4];
    const float* wk   = (const float*)d_in[5];
    const float* wv   = (const float*)d_in[6];
    const float* wo   = (const float*)d_in[7];
    const float* wg   = (const float*)d_in[8];
    const float* wu   = (const float*)d_in[9];
    const float* wd   = (const float*)d_in[10];
    const float* ln1  = (const float*)d_in[11];
    const float* ln2  = (const float*)d_in[12];
    float* out = (float*)d_out;

    cudaFuncSetAttribute(mma_gemm1_kernel,
                         cudaFuncAttributeMaxDynamicSharedMemorySize, SM1);
    cudaFuncSetAttribute(mma_gemm3_kernel,
                         cudaFuncAttributeMaxDynamicSharedMemorySize, SM3);
    cudaFuncSetAttribute(mma_scores_kernel,
                         cudaFuncAttributeMaxDynamicSharedMemorySize, SM1);
    cudaFuncSetAttribute(mma_pv_kernel,
                         cudaFuncAttributeMaxDynamicSharedMemorySize, SM1);

    bf16 *x1h, *qh, *kh, *ctxh, *x2h, *x2l, *mh, *ml;
    bf16 *wqth, *wkth, *wvth, *woth;
    bf16 *wgth, *wgtl, *wuth, *wutl, *wdth, *wdtl;
    float *q, *k, *v, *ctx, *h2, *gate, *up;
    cudaGetSymbolAddress((void**)&x1h, g_x1h);
    cudaGetSymbolAddress((void**)&qh,  g_qh);
    cudaGetSymbolAddress((void**)&kh,  g_kh);
    cudaGetSymbolAddress((void**)&ctxh,g_ctxh);
    cudaGetSymbolAddress((void**)&x2h, g_x2h); cudaGetSymbolAddress((void**)&x2l, g_x2l);
    cudaGetSymbolAddress((void**)&mh,  g_mh);  cudaGetSymbolAddress((void**)&ml,  g_ml);
    cudaGetSymbolAddress((void**)&wqth,g_wqt_h);
    cudaGetSymbolAddress((void**)&wkth,g_wkt_h);
    cudaGetSymbolAddress((void**)&wvth,g_wvt_h);
    cudaGetSymbolAddress((void**)&woth,g_wot_h);
    cudaGetSymbolAddress((void**)&wgth,g_wgt_h);cudaGetSymbolAddress((void**)&wgtl,g_wgt_l);
    cudaGetSymbolAddress((void**)&wuth,g_wut_h);cudaGetSymbolAddress((void**)&wutl,g_wut_l);
    cudaGetSymbolAddress((void**)&wdth,g_wdt_h);cudaGetSymbolAddress((void**)&wdtl,g_wdt_l);
    cudaGetSymbolAddress((void**)&q,   g_q);   cudaGetSymbolAddress((void**)&k,   g_k);
    cudaGetSymbolAddress((void**)&v,   g_v);   cudaGetSymbolAddress((void**)&ctx, g_ctx);
    cudaGetSymbolAddress((void**)&h2,  g_h2);
    cudaGetSymbolAddress((void**)&gate,g_gate);cudaGetSymbolAddress((void**)&up,  g_up);

    // 1) x1 = rmsnorm(hs) -> bf16 (hi only; feeds 1-term QKV)
    rmsnorm_split_kernel<<<TOK, 256>>>(hs, ln1, x1h, nullptr);

    // 2) weight transpose(+split): W[K,N] -> Wt[N,K]
    transpose_split_kernel<<<dim3(DMODEL/32, DMODEL/32), 256>>>(wq, wqth, nullptr, DMODEL, DMODEL);
    transpose_split_kernel<<<dim3(DKV/32,    DMODEL/32), 256>>>(wk, wkth, nullptr, DMODEL, DKV);
    transpose_split_kernel<<<dim3(DKV/32,    DMODEL/32), 256>>>(wv, wvth, nullptr, DMODEL, DKV);
    transpose_split_kernel<<<dim3(DMODEL/32, DMODEL/32), 256>>>(wo, woth, nullptr, DMODEL, DMODEL);
    transpose_split_kernel<<<dim3(DFF/32,    DMODEL/32), 256>>>(wg, wgth, wgtl, DMODEL, DFF);
    transpose_split_kernel<<<dim3(DFF/32,    DMODEL/32), 256>>>(wu, wuth, wutl, DMODEL, DFF);
    transpose_split_kernel<<<dim3(DMODEL/32, DFF/32),    256>>>(wd, wdth, wdtl, DFF, DMODEL);

    // 3) QKV projections (1-term bf16, fp32 out)
    mma_gemm1_kernel<<<dim3(DMODEL/128, TOK/128), 256, SM1>>>(
        x1h, DMODEL, wqth, DMODEL, nullptr, q, DMODEL, DMODEL);
    mma_gemm1_kernel<<<dim3(DKV/128, TOK/128), 256, SM1>>>(
        x1h, DMODEL, wkth, DMODEL, nullptr, k, DKV, DMODEL);
    mma_gemm1_kernel<<<dim3(DKV/128, TOK/128), 256, SM1>>>(
        x1h, DMODEL, wvth, DMODEL, nullptr, v, DKV, DMODEL);

    // 4) RoPE -> bf16; V transpose -> bf16
    rope_kernel<<<dim3(TOK, NHEADS), 64>>>(q, cosp, sinp, qh, DMODEL);
    rope_kernel<<<dim3(TOK, NKV),    64>>>(k, cosp, sinp, kh, DKV);
    vT_kernel<<<dim3(HD/32, SEQ/32, BATCH*NKV), 256>>>();

    // 5) scores = Q K^T
    mma_scores_kernel<<<dim3(SEQ/128, SEQ/128, BATCH*NHEADS), 256, SM1>>>();

    // 6) softmax -> P bf16
    softmax_kernel<<<dim3(SEQ, BATCH*NHEADS), 256>>>(mask);

    // 7) ctx = P V
    mma_pv_kernel<<<dim3(1, SEQ/128, BATCH*NHEADS), 256, SM1>>>();

    // 8) h2 = hs + ctx @ wo
    ctx_cvt_kernel<<<(unsigned)((long)TOK*DMODEL/256), 256>>>();
    mma_gemm1_kernel<<<dim3(DMODEL/128, TOK/128), 256, SM1>>>(
        ctxh, DMODEL, woth, DMODEL, hs, h2, DMODEL, DMODEL);

    // 9) x2 = rmsnorm(h2) -> hi/lo (feeds 3-term MLP)
    rmsnorm_split_kernel<<<TOK, 256>>>(h2, ln2, x2h, x2l);

    // 10) MLP (3-term split)
    mma_gemm3_kernel<<<dim3(DFF/128, TOK/128), 256, SM3>>>(
        x2h, x2l, DMODEL, wgth, wgtl, DMODEL, nullptr, gate, DFF, DMODEL);
    mma_gemm3_kernel<<<dim3(DFF/128, TOK/128), 256, SM3>>>(
        x2h, x2l, DMODEL, wuth, wutl, DMODEL, nullptr, up, DFF, DMODEL);
    silu_split_kernel<<<(unsigned)((long)TOK*DFF/256), 256>>>();

    // 11) out = h2 + (silu(gate)*up) @ wd  (3-term split)
    mma_gemm3_kernel<<<dim3(DMODEL/128, TOK/128), 256, SM3>>>(
        mh, ml, DFF, wdth, wdtl, DFF, h2, out, DMODEL, DFF);
}

// round 5
// speedup vs baseline: 2.9164x; 1.1318x over previous
#include <cuda_runtime.h>
#include <cuda_bf16.h>
#include <math.h>
#include <stdint.h>

// ---------------------------------------------------------------------------
// Problem constants
// ---------------------------------------------------------------------------
constexpr int BATCH   = 2;
constexpr int SEQ     = 2048;
constexpr int DMODEL  = 2048;
constexpr int DFF     = 8192;
constexpr int NHEADS  = 16;
constexpr int NKV     = 8;
constexpr int HD      = 128;
constexpr int DKV     = NKV * HD;      // 1024
constexpr int TOK     = BATCH * SEQ;   // 4096
constexpr float EPSV  = 1e-5f;
constexpr float SM_SCALE = 0.08838834764831845f; // 128^-0.5

typedef __nv_bfloat16 bf16;

// ---------------------------------------------------------------------------
// Scratch (device globals; allocation anywhere is forbidden)
// ---------------------------------------------------------------------------
__device__ bf16  g_x1h [(size_t)TOK * DMODEL];
__device__ float g_q   [(size_t)TOK * DMODEL];
__device__ float g_k   [(size_t)TOK * DKV];
__device__ float g_v   [(size_t)TOK * DKV];
__device__ bf16  g_qh  [(size_t)TOK * DMODEL];
__device__ bf16  g_kh  [(size_t)TOK * DKV];
__device__ bf16  g_vth [(size_t)TOK * DKV];   // V^T: [(b*8+kh)][128][SEQ]
__device__ float g_scores[(size_t)BATCH * NHEADS * SEQ * SEQ]; // 536 MB
__device__ bf16  g_ph  [(size_t)BATCH * NHEADS * SEQ * SEQ];
__device__ bf16  g_ctxh[(size_t)TOK * DMODEL];
__device__ float g_h2  [(size_t)TOK * DMODEL];
__device__ bf16  g_x2h [(size_t)TOK * DMODEL];
__device__ bf16  g_x2l [(size_t)TOK * DMODEL];
__device__ float g_gate[(size_t)TOK * DFF];
__device__ float g_up  [(size_t)TOK * DFF];
__device__ bf16  g_mh  [(size_t)TOK * DFF];
__device__ bf16  g_ml  [(size_t)TOK * DFF];
// transposed-converted weights: [N, K]
__device__ bf16  g_wqt_h[(size_t)DMODEL * DMODEL];
__device__ bf16  g_wkt_h[(size_t)DKV * DMODEL];
__device__ bf16  g_wvt_h[(size_t)DKV * DMODEL];
__device__ bf16  g_wot_h[(size_t)DMODEL * DMODEL];
__device__ bf16  g_wgt_h[(size_t)DFF * DMODEL];
__device__ bf16  g_wgt_l[(size_t)DFF * DMODEL];
__device__ bf16  g_wut_h[(size_t)DFF * DMODEL];
__device__ bf16  g_wut_l[(size_t)DFF * DMODEL];
__device__ bf16  g_wdt_h[(size_t)DMODEL * DFF];
__device__ bf16  g_wdt_l[(size_t)DMODEL * DFF];

// ---------------------------------------------------------------------------
// PTX helpers — baseline sm_80+ only (harness targets plain sm_103: no tcgen05)
// ---------------------------------------------------------------------------
__device__ __forceinline__ uint32_t smem_u32(const void* p) {
    uint32_t a;
    asm("{ .reg .u64 t; cvta.to.shared.u64 t, %1; cvt.u32.u64 %0, t; }"
        : "=r"(a) : "l"(p));
    return a;
}

__device__ __forceinline__ void cp16(uint32_t saddr, const void* g) {
    unsigned long long ga = (unsigned long long)__cvta_generic_to_global(g);
    asm volatile("cp.async.cg.shared.global [%0], [%1], 16;\n"
                 :: "r"(saddr), "l"(ga));
}
#define CP_COMMIT() asm volatile("cp.async.commit_group;\n" ::: "memory")
template <int N>
__device__ __forceinline__ void cp_wait() {
    asm volatile("cp.async.wait_group %0;\n" :: "n"(N) : "memory");
}

__device__ __forceinline__ void ldmx4(uint32_t* r, uint32_t addr) {
    asm volatile("ldmatrix.sync.aligned.m8n8.x4.shared.b16 {%0,%1,%2,%3}, [%4];\n"
        : "=r"(r[0]), "=r"(r[1]), "=r"(r[2]), "=r"(r[3]) : "r"(addr));
}

__device__ __forceinline__ void mma16816(float* c, const uint32_t* a, const uint32_t* b) {
    asm volatile(
        "mma.sync.aligned.m16n8k16.row.col.f32.bf16.bf16.f32 "
        "{%0,%1,%2,%3}, {%4,%5,%6,%7}, {%8,%9}, {%0,%1,%2,%3};\n"
        : "+f"(c[0]), "+f"(c[1]), "+f"(c[2]), "+f"(c[3])
        : "r"(a[0]), "r"(a[1]), "r"(a[2]), "r"(a[3]), "r"(b[0]), "r"(b[1]));
}

__device__ __forceinline__ void split2(float v, bf16& h, bf16& l) {
    h = __float2bfloat16(v);
    l = __float2bfloat16(v - __bfloat162float(h));
}

// ---------------------------------------------------------------------------
// MMA GEMM: C[128 x 128] tile of A[M,K] * Bt[N,K]^T (+ R), out fp32 or bf16.
// NT=1: plain bf16. NT=3: 3-term hi/lo split (~fp32 accuracy).
// 128 threads, 4 warps in 2x2, warp tile 64x64. BK=32.
// smem rows: 32 bf16 = 64B padded to 80B (ldmatrix conflict-free).
// Multistage cp.async: 3 stages (NT=1) / 2 stages (NT=3), 1 sync per chunk.
// ---------------------------------------------------------------------------
constexpr int LDSS = 80;                 // smem row stride bytes
constexpr int MATB = 128 * LDSS;         // 10240 B per matrix per stage

template <int NT>
__device__ __forceinline__ void load_stage(
    uint32_t sb, int s, const bf16* __restrict__ Ah, const bf16* __restrict__ Al,
    const bf16* __restrict__ Bh, const bf16* __restrict__ Bl,
    long lda, long ldb, int k0, int tid)
{
    constexpr int STAGE = (NT == 3 ? 4 : 2) * MATB;
    uint32_t base = sb + (uint32_t)(s * STAGE);
    #pragma unroll
    for (int i = 0; i < 4; i++) {
        int idx = tid + i * 128;                 // 0..511
        int r = idx >> 2, cb = (idx & 3) << 4;   // row, k-byte offset
        uint32_t so = (uint32_t)(r * LDSS + cb);
        long ga = (long)r * lda + k0 + (cb >> 1);
        long gb = (long)r * ldb + k0 + (cb >> 1);
        cp16(base + so, Ah + ga);
        if (NT == 3) cp16(base + MATB + so, Al + ga);
        cp16(base + (NT == 3 ? 2 : 1) * MATB + so, Bh + gb);
        if (NT == 3) cp16(base + 3 * MATB + so, Bl + gb);
    }
}

template <int NT>
__device__ __forceinline__ void compute_stage(
    uint32_t sb, int s, int wm, int wn, int l, float acc[4][8][4])
{
    constexpr int STAGE = (NT == 3 ? 4 : 2) * MATB;
    uint32_t As  = sb + (uint32_t)(s * STAGE);
    uint32_t Als = As + MATB;
    uint32_t Bs  = As + (NT == 3 ? 2 : 1) * MATB;
    uint32_t Bls = Bs + MATB;
    uint32_t a_off = (uint32_t)((wm * 64 + (l & 15)) * LDSS + ((l >> 4) << 4));
    uint32_t b_off = (uint32_t)((wn * 64 + ((l >> 4) << 3) + (l & 7)) * LDSS
                                + (((l >> 3) & 1) << 4));
    #pragma unroll
    for (int kk = 0; kk < 2; kk++) {
        uint32_t kb = (uint32_t)(kk * 32);   // 16 elems = 32 B
        uint32_t ah[4][4], bh[8][2];
        #pragma unroll
        for (int m = 0; m < 4; m++)
            ldmx4(ah[m], As + a_off + m * (16 * LDSS) + kb);
        #pragma unroll
        for (int p = 0; p < 4; p++) {
            uint32_t r[4];
            ldmx4(r, Bs + b_off + p * (16 * LDSS) + kb);
            bh[2*p][0] = r[0]; bh[2*p][1] = r[1];
            bh[2*p+1][0] = r[2]; bh[2*p+1][1] = r[3];
        }
        #pragma unroll
        for (int m = 0; m < 4; m++)
            #pragma unroll
            for (int n = 0; n < 8; n++)
                mma16816(acc[m][n], ah[m], bh[n]);
        if (NT == 3) {
            uint32_t al[4][4], bl[8][2];
            #pragma unroll
            for (int m = 0; m < 4; m++)
                ldmx4(al[m], Als + a_off + m * (16 * LDSS) + kb);
            #pragma unroll
            for (int p = 0; p < 4; p++) {
                uint32_t r[4];
                ldmx4(r, Bls + b_off + p * (16 * LDSS) + kb);
                bl[2*p][0] = r[0]; bl[2*p][1] = r[1];
                bl[2*p+1][0] = r[2]; bl[2*p+1][1] = r[3];
            }
            #pragma unroll
            for (int m = 0; m < 4; m++)
                #pragma unroll
                for (int n = 0; n < 8; n++) {
                    mma16816(acc[m][n], ah[m], bl[n]);
                    mma16816(acc[m][n], al[m], bh[n]);
                }
        }
    }
}

template <int NT, int OB>
__device__ __forceinline__ void gemm_mma(
    const bf16* __restrict__ a_hi, const bf16* __restrict__ a_lo, long lda,
    const bf16* __restrict__ b_hi, const bf16* __restrict__ b_lo, long ldb,
    const float* __restrict__ R, void* __restrict__ Cv, long ldc,
    int K, int m0, int n0)
{
    constexpr int S = (NT == 3) ? 2 : 3;
    extern __shared__ char smem[];
    uint32_t sb = smem_u32(smem);
    const int tid = threadIdx.x, wid = tid >> 5, l = tid & 31;
    const int wm = wid & 1, wn = wid >> 1;

    const bf16* Ah = a_hi + (long)m0 * lda;
    const bf16* Al = (NT == 3) ? a_lo + (long)m0 * lda : Ah;
    const bf16* Bh = b_hi + (long)n0 * ldb;
    const bf16* Bl = (NT == 3) ? b_lo + (long)n0 * ldb : Bh;

    float acc[4][8][4];
    #pragma unroll
    for (int m = 0; m < 4; m++)
        #pragma unroll
        for (int n = 0; n < 8; n++)
            #pragma unroll
            for (int i = 0; i < 4; i++) acc[m][n][i] = 0.f;

    const int nk = K >> 5;
    #pragma unroll
    for (int c = 0; c < S - 1; c++) {
        load_stage<NT>(sb, c, Ah, Al, Bh, Bl, lda, ldb, c * 32, tid);
        CP_COMMIT();
    }
    int slot_c = 0, slot_p = (S - 1) % S;
    for (int c = 0; c < nk; c++) {
        cp_wait<S - 2>();
        __syncthreads();
        if (c + S - 1 < nk)
            load_stage<NT>(sb, slot_p, Ah, Al, Bh, Bl, lda, ldb,
                           (c + S - 1) * 32, tid);
        CP_COMMIT();
        compute_stage<NT>(sb, slot_c, wm, wn, l, acc);
        slot_c = (slot_c + 1 == S) ? 0 : slot_c + 1;
        slot_p = (slot_p + 1 == S) ? 0 : slot_p + 1;
    }

    // epilogue
    const int row0 = m0 + wm * 64, col0 = n0 + wn * 64;
    #pragma unroll
    for (int m = 0; m < 4; m++) {
        int r0 = row0 + m * 16 + (l >> 2);
        #pragma unroll
        for (int n = 0; n < 8; n++) {
            int cc = col0 + n * 8 + (l & 3) * 2;
            float2 v0 = make_float2(acc[m][n][0], acc[m][n][1]);
            float2 v1 = make_float2(acc[m][n][2], acc[m][n][3]);
            if (OB == 0) {
                float* C = (float*)Cv;
                if (R) {
                    float2 q0 = *(const float2*)(R + (long)r0 * ldc + cc);
                    float2 q1 = *(const float2*)(R + (long)(r0 + 8) * ldc + cc);
                    v0.x += q0.x; v0.y += q0.y; v1.x += q1.x; v1.y += q1.y;
                }
                *(float2*)(C + (long)r0 * ldc + cc)       = v0;
                *(float2*)(C + (long)(r0 + 8) * ldc + cc) = v1;
            } else {
                bf16* C = (bf16*)Cv;
                __nv_bfloat162 b0, b1;
                b0.x = __float2bfloat16(v0.x); b0.y = __float2bfloat16(v0.y);
                b1.x = __float2bfloat16(v1.x); b1.y = __float2bfloat16(v1.y);
                *(__nv_bfloat162*)(C + (long)r0 * ldc + cc)       = b0;
                *(__nv_bfloat162*)(C + (long)(r0 + 8) * ldc + cc) = b1;
            }
        }
    }
}

constexpr int SM1 = 3 * 2 * MATB;   // 61440
constexpr int SM3 = 2 * 4 * MATB;   // 81920

// ---------------------------------------------------------------------------
// GEMM wrapper kernels
// ---------------------------------------------------------------------------
__global__ __launch_bounds__(128) void mma_gemm1_kernel(
    const bf16* a, long lda, const bf16* b, long ldb,
    const float* R, float* C, long ldc, int K)
{
    gemm_mma<1, 0>(a, nullptr, lda, b, nullptr, ldb, R, C, ldc, K,
                   blockIdx.y * 128, blockIdx.x * 128);
}

__global__ __launch_bounds__(128) void mma_gemm3_kernel(
    const bf16* ah, const bf16* al, long lda,
    const bf16* bh, const bf16* bl, long ldb,
    const float* R, float* C, long ldc, int K)
{
    gemm_mma<3, 0>(ah, al, lda, bh, bl, ldb, R, C, ldc, K,
                   blockIdx.y * 128, blockIdx.x * 128);
}

__global__ __launch_bounds__(128) void mma_scores_kernel()
{
    int z = blockIdx.z, b = z >> 4, h = z & 15, kh = h >> 1;
    const bf16* A = g_qh + (long)b * SEQ * DMODEL + h * HD;
    const bf16* B = g_kh + (long)b * SEQ * DKV + kh * HD;
    float* C = g_scores + (long)z * SEQ * SEQ;
    gemm_mma<1, 0>(A, nullptr, DMODEL, B, nullptr, DKV, nullptr, C, SEQ, HD,
                   blockIdx.y * 128, blockIdx.x * 128);
}

// PV: writes bf16 ctx directly (fused convert)
__global__ __launch_bounds__(128) void mma_pv_kernel()
{
    int z = blockIdx.z, b = z >> 4, h = z & 15, kh = h >> 1;
    const bf16* A = g_ph + (long)z * SEQ * SEQ;
    const bf16* B = g_vth + (long)(b * NKV + kh) * HD * SEQ;
    bf16* C = g_ctxh + (long)b * SEQ * DMODEL + h * HD;
    gemm_mma<1, 1>(A, nullptr, SEQ, B, nullptr, SEQ, nullptr, C, DMODEL, SEQ,
                   blockIdx.y * 128, 0);
}

// ---------------------------------------------------------------------------
// Reductions
// ---------------------------------------------------------------------------
__device__ __forceinline__ float block_reduce_sum(float v)
{
    __shared__ float red[32];
    int lid = threadIdx.x & 31, wid = threadIdx.x >> 5;
    #pragma unroll
    for (int o = 16; o; o >>= 1) v += __shfl_xor_sync(0xffffffffu, v, o);
    if (lid == 0) red[wid] = v;
    __syncthreads();
    v = (threadIdx.x < 8) ? red[threadIdx.x] : 0.f;
    if (wid == 0) {
        #pragma unroll
        for (int o = 4; o; o >>= 1) v += __shfl_xor_sync(0xffffffffu, v, o);
        if (lid == 0) red[0] = v;
    }
    __syncthreads();
    return red[0];
}
__device__ __forceinline__ float block_reduce_max(float v)
{
    __shared__ float red[32];
    int lid = threadIdx.x & 31, wid = threadIdx.x >> 5;
    #pragma unroll
    for (int o = 16; o; o >>= 1) v = fmaxf(v, __shfl_xor_sync(0xffffffffu, v, o));
    if (lid == 0) red[wid] = v;
    __syncthreads();
    v = (threadIdx.x < 8) ? red[threadIdx.x] : -INFINITY;
    if (wid == 0) {
        #pragma unroll
        for (int o = 4; o; o >>= 1) v = fmaxf(v, __shfl_xor_sync(0xffffffffu, v, o));
        if (lid == 0) red[0] = v;
    }
    __syncthreads();
    return red[0];
}

// ---------------------------------------------------------------------------
// RMSNorm -> bf16 hi (+ optional lo)
// ---------------------------------------------------------------------------
__global__ __launch_bounds__(256) void rmsnorm_split_kernel(
    const float* __restrict__ x, const float* __restrict__ w,
    bf16* __restrict__ oh, bf16* __restrict__ ol)
{
    long row = blockIdx.x;
    const float* xr = x + row * DMODEL;
    float vals[8];
    float ss = 0.f;
    #pragma unroll
    for (int i = 0; i < 8; i++) {
        int idx = threadIdx.x + i * 256;
        vals[i] = xr[idx];
        ss = fmaf(vals[i], vals[i], ss);
    }
    float total = block_reduce_sum(ss);
    float rstd = rsqrtf(total * (1.0f / DMODEL) + EPSV);
    #pragma unroll
    for (int i = 0; i < 8; i++) {
        int idx = threadIdx.x + i * 256;
        float v = vals[i] * rstd * w[idx];
        bf16 h, l; split2(v, h, l);
        oh[row * DMODEL + idx] = h;
        if (ol) ol[row * DMODEL + idx] = l;
    }
}

// ---------------------------------------------------------------------------
// RoPE (HF-style) fp32 -> bf16
// ---------------------------------------------------------------------------
__global__ __launch_bounds__(64) void rope_kernel(
    const float* __restrict__ x, const float* __restrict__ cs,
    const float* __restrict__ sn, bf16* __restrict__ oh, int ld)
{
    long base = (long)blockIdx.x * ld + blockIdx.y * HD;
    int j = threadIdx.x;
    float e = x[base + 2 * j];
    float o = x[base + 2 * j + 1];
    float c = cs[(long)blockIdx.x * 64 + j];
    float s = sn[(long)blockIdx.x * 64 + j];
    oh[base + j]      = __float2bfloat16(e * c - o * s);
    oh[base + 64 + j] = __float2bfloat16(e * s + o * c);
}

// ---------------------------------------------------------------------------
// Weight transpose + split: in [RI, CI] fp32 -> out [CI, RI] bf16 hi (+lo)
// ---------------------------------------------------------------------------
__global__ __launch_bounds__(256) void transpose_split_kernel(
    const float* __restrict__ in, bf16* __restrict__ oh, bf16* __restrict__ ol,
    int RI, int CI)
{
    __shared__ float t[32][33];
    int tx = threadIdx.x & 31, ty = threadIdx.x >> 5;
    int r0 = blockIdx.y * 32, c0 = blockIdx.x * 32;
    #pragma unroll
    for (int i = 0; i < 4; i++)
        t[ty + i * 8][tx] = in[(long)(r0 + ty + i * 8) * CI + c0 + tx];
    __syncthreads();
    #pragma unroll
    for (int i = 0; i < 4; i++) {
        float v = t[tx][ty + i * 8];
        long o = (long)(c0 + ty + i * 8) * RI + r0 + tx;
        bf16 h, l; split2(v, h, l);
        oh[o] = h;
        if (ol) ol[o] = l;
    }
}

// V transpose: g_v [b, s, kh*128+d] -> g_vth [(b*8+kh)][d][s] bf16
__global__ __launch_bounds__(256) void vT_kernel()
{
    __shared__ float t[32][33];
    int z = blockIdx.z;
    int b = z >> 3, kh = z & 7;
    const float* in = g_v + (long)b * SEQ * DKV + kh * HD;
    bf16* oh = g_vth + (long)z * HD * SEQ;
    int tx = threadIdx.x & 31, ty = threadIdx.x >> 5;
    int s0 = blockIdx.y * 32, d0 = blockIdx.x * 32;
    #pragma unroll
    for (int i = 0; i < 4; i++)
        t[ty + i * 8][tx] = in[(long)(s0 + ty + i * 8) * DKV + d0 + tx];
    __syncthreads();
    #pragma unroll
    for (int i = 0; i < 4; i++)
        oh[(long)(d0 + ty + i * 8) * SEQ + s0 + tx] =
            __float2bfloat16(t[tx][ty + i * 8]);
}

// ---------------------------------------------------------------------------
// Softmax (scale + mask) -> bf16
// ---------------------------------------------------------------------------
__global__ __launch_bounds__(256) void softmax_kernel(const float* __restrict__ mask)
{
    int z = blockIdx.y;
    int b = z >> 4;
    long row = blockIdx.x;
    const float* srow = g_scores + ((long)z * SEQ + row) * SEQ;
    const float* mrow = mask + ((long)b * SEQ + row) * SEQ;
    bf16* phr = g_ph + ((long)z * SEQ + row) * SEQ;

    float v[8];
    float mx = -INFINITY;
    #pragma unroll
    for (int i = 0; i < 8; i++) {
        int idx = threadIdx.x + i * 256;
        v[i] = fmaf(srow[idx], SM_SCALE, mrow[idx]);
        mx = fmaxf(mx, v[i]);
    }
    float bm = block_reduce_max(mx);
    float sum = 0.f;
    #pragma unroll
    for (int i = 0; i < 8; i++) {
        v[i] = expf(v[i] - bm);
        sum += v[i];
    }
    float total = block_reduce_sum(sum);
    float inv = 1.0f / total;
    #pragma unroll
    for (int i = 0; i < 8; i++) {
        int idx = threadIdx.x + i * 256;
        phr[idx] = __float2bfloat16(v[i] * inv);
    }
}

// ---------------------------------------------------------------------------
// SwiGLU -> bf16 hi/lo
// ---------------------------------------------------------------------------
__global__ __launch_bounds__(256) void silu_split_kernel()
{
    long i = (long)blockIdx.x * 256 + threadIdx.x;
    float g = g_gate[i], u = g_up[i];
    float v = u * g / (1.0f + expf(-g));
    bf16 h, l; split2(v, h, l);
    g_mh[i] = h; g_ml[i] = l;
}

// ---------------------------------------------------------------------------
// Launch
// ---------------------------------------------------------------------------
extern "C" void kernel_launch(void* const* d_in, const int* in_sizes, int n_in,
                              void* d_out, int out_size)
{
    const float* hs   = (const float*)d_in[0];
    const float* cosp = (const float*)d_in[1];
    const float* sinp = (const float*)d_in[2];
    const float* mask = (const float*)d_in[3];
    const float* wq   = (const float*)d_in[4];
    const float* wk   = (const float*)d_in[5];
    const float* wv   = (const float*)d_in[6];
    const float* wo   = (const float*)d_in[7];
    const float* wg   = (const float*)d_in[8];
    const float* wu   = (const float*)d_in[9];
    const float* wd   = (const float*)d_in[10];
    const float* ln1  = (const float*)d_in[11];
    const float* ln2  = (const float*)d_in[12];
    float* out = (float*)d_out;

    cudaFuncSetAttribute(mma_gemm1_kernel,
                         cudaFuncAttributeMaxDynamicSharedMemorySize, SM1);
    cudaFuncSetAttribute(mma_gemm3_kernel,
                         cudaFuncAttributeMaxDynamicSharedMemorySize, SM3);
    cudaFuncSetAttribute(mma_scores_kernel,
                         cudaFuncAttributeMaxDynamicSharedMemorySize, SM1);
    cudaFuncSetAttribute(mma_pv_kernel,
                         cudaFuncAttributeMaxDynamicSharedMemorySize, SM1);

    bf16 *x1h, *qh, *kh, *ctxh, *x2h, *x2l, *mh, *ml;
    bf16 *wqth, *wkth, *wvth, *woth;
    bf16 *wgth, *wgtl, *wuth, *wutl, *wdth, *wdtl;
    float *q, *k, *v, *h2, *gate, *up;
    cudaGetSymbolAddress((void**)&x1h, g_x1h);
    cudaGetSymbolAddress((void**)&qh,  g_qh);
    cudaGetSymbolAddress((void**)&kh,  g_kh);
    cudaGetSymbolAddress((void**)&ctxh,g_ctxh);
    cudaGetSymbolAddress((void**)&x2h, g_x2h); cudaGetSymbolAddress((void**)&x2l, g_x2l);
    cudaGetSymbolAddress((void**)&mh,  g_mh);  cudaGetSymbolAddress((void**)&ml,  g_ml);
    cudaGetSymbolAddress((void**)&wqth,g_wqt_h);
    cudaGetSymbolAddress((void**)&wkth,g_wkt_h);
    cudaGetSymbolAddress((void**)&wvth,g_wvt_h);
    cudaGetSymbolAddress((void**)&woth,g_wot_h);
    cudaGetSymbolAddress((void**)&wgth,g_wgt_h);cudaGetSymbolAddress((void**)&wgtl,g_wgt_l);
    cudaGetSymbolAddress((void**)&wuth,g_wut_h);cudaGetSymbolAddress((void**)&wutl,g_wut_l);
    cudaGetSymbolAddress((void**)&wdth,g_wdt_h);cudaGetSymbolAddress((void**)&wdtl,g_wdt_l);
    cudaGetSymbolAddress((void**)&q,   g_q);   cudaGetSymbolAddress((void**)&k,   g_k);
    cudaGetSymbolAddress((void**)&v,   g_v);
    cudaGetSymbolAddress((void**)&h2,  g_h2);
    cudaGetSymbolAddress((void**)&gate,g_gate);cudaGetSymbolAddress((void**)&up,  g_up);

    // 1) x1 = rmsnorm(hs) -> bf16 (hi only; feeds 1-term QKV)
    rmsnorm_split_kernel<<<TOK, 256>>>(hs, ln1, x1h, nullptr);

    // 2) weight transpose(+split): W[K,N] -> Wt[N,K]
    transpose_split_kernel<<<dim3(DMODEL/32, DMODEL/32), 256>>>(wq, wqth, nullptr, DMODEL, DMODEL);
    transpose_split_kernel<<<dim3(DKV/32,    DMODEL/32), 256>>>(wk, wkth, nullptr, DMODEL, DKV);
    transpose_split_kernel<<<dim3(DKV/32,    DMODEL/32), 256>>>(wv, wvth, nullptr, DMODEL, DKV);
    transpose_split_kernel<<<dim3(DMODEL/32, DMODEL/32), 256>>>(wo, woth, nullptr, DMODEL, DMODEL);
    transpose_split_kernel<<<dim3(DFF/32,    DMODEL/32), 256>>>(wg, wgth, wgtl, DMODEL, DFF);
    transpose_split_kernel<<<dim3(DFF/32,    DMODEL/32), 256>>>(wu, wuth, wutl, DMODEL, DFF);
    transpose_split_kernel<<<dim3(DMODEL/32, DFF/32),    256>>>(wd, wdth, wdtl, DFF, DMODEL);

    // 3) QKV projections (1-term bf16, fp32 out)
    mma_gemm1_kernel<<<dim3(DMODEL/128, TOK/128), 128, SM1>>>(
        x1h, DMODEL, wqth, DMODEL, nullptr, q, DMODEL, DMODEL);
    mma_gemm1_kernel<<<dim3(DKV/128, TOK/128), 128, SM1>>>(
        x1h, DMODEL, wkth, DMODEL, nullptr, k, DKV, DMODEL);
    mma_gemm1_kernel<<<dim3(DKV/128, TOK/128), 128, SM1>>>(
        x1h, DMODEL, wvth, DMODEL, nullptr, v, DKV, DMODEL);

    // 4) RoPE -> bf16; V transpose -> bf16
    rope_kernel<<<dim3(TOK, NHEADS), 64>>>(q, cosp, sinp, qh, DMODEL);
    rope_kernel<<<dim3(TOK, NKV),    64>>>(k, cosp, sinp, kh, DKV);
    vT_kernel<<<dim3(HD/32, SEQ/32, BATCH*NKV), 256>>>();

    // 5) scores = Q K^T
    mma_scores_kernel<<<dim3(SEQ/128, SEQ/128, BATCH*NHEADS), 128, SM1>>>();

    // 6) softmax -> P bf16
    softmax_kernel<<<dim3(SEQ, BATCH*NHEADS), 256>>>(mask);

    // 7) ctx = P V (writes bf16 directly)
    mma_pv_kernel<<<dim3(1, SEQ/128, BATCH*NHEADS), 128, SM1>>>();

    // 8) h2 = hs + ctx @ wo
    mma_gemm1_kernel<<<dim3(DMODEL/128, TOK/128), 128, SM1>>>(
        ctxh, DMODEL, woth, DMODEL, hs, h2, DMODEL, DMODEL);

    // 9) x2 = rmsnorm(h2) -> hi/lo (feeds 3-term MLP)
    rmsnorm_split_kernel<<<TOK, 256>>>(h2, ln2, x2h, x2l);

    // 10) MLP (3-term split)
    mma_gemm3_kernel<<<dim3(DFF/128, TOK/128), 128, SM3>>>(
        x2h, x2l, DMODEL, wgth, wgtl, DMODEL, nullptr, gate, DFF, DMODEL);
    mma_gemm3_kernel<<<dim3(DFF/128, TOK/128), 128, SM3>>>(
        x2h, x2l, DMODEL, wuth, wutl, DMODEL, nullptr, up, DFF, DMODEL);
    silu_split_kernel<<<(unsigned)((long)TOK*DFF/256), 256>>>();

    // 11) out = h2 + (silu(gate)*up) @ wd  (3-term split)
    mma_gemm3_kernel<<<dim3(DMODEL/128, TOK/128), 128, SM3>>>(
        mh, ml, DFF, wdth, wdtl, DFF, h2, out, DMODEL, DFF);
}

// round 7
// speedup vs baseline: 3.2850x; 1.1264x over previous
#include <cuda_runtime.h>
#include <cuda_bf16.h>
#include <math.h>
#include <stdint.h>

// ---------------------------------------------------------------------------
// Problem constants
// ---------------------------------------------------------------------------
constexpr int BATCH   = 2;
constexpr int SEQ     = 2048;
constexpr int DMODEL  = 2048;
constexpr int DFF     = 8192;
constexpr int NHEADS  = 16;
constexpr int NKV     = 8;
constexpr int HD      = 128;
constexpr int DKV     = NKV * HD;      // 1024
constexpr int TOK     = BATCH * SEQ;   // 4096
constexpr float EPSV  = 1e-5f;
constexpr float SM_SCALE = 0.08838834764831845f; // 128^-0.5

typedef __nv_bfloat16 bf16;

// ---------------------------------------------------------------------------
// Scratch (device globals; allocation anywhere is forbidden)
// ---------------------------------------------------------------------------
__device__ bf16  g_x1h [(size_t)TOK * DMODEL];
__device__ float g_q   [(size_t)TOK * DMODEL];
__device__ float g_k   [(size_t)TOK * DKV];
__device__ float g_v   [(size_t)TOK * DKV];
__device__ bf16  g_qh  [(size_t)TOK * DMODEL];
__device__ bf16  g_kh  [(size_t)TOK * DKV];
__device__ bf16  g_vth [(size_t)TOK * DKV];   // V^T: [(b*8+kh)][128][SEQ]
__device__ float g_scores[(size_t)BATCH * NHEADS * SEQ * SEQ]; // 536 MB
__device__ bf16  g_ph  [(size_t)BATCH * NHEADS * SEQ * SEQ];
__device__ bf16  g_ctxh[(size_t)TOK * DMODEL];
__device__ float g_h2  [(size_t)TOK * DMODEL];
__device__ float g_x2t [(size_t)TOK * DMODEL];   // tf32-rounded fp32
__device__ float g_gate[(size_t)TOK * DFF];
__device__ float g_up  [(size_t)TOK * DFF];
__device__ float g_mt  [(size_t)TOK * DFF];      // tf32-rounded fp32
// transposed weights
__device__ bf16  g_wqt_h[(size_t)DMODEL * DMODEL];
__device__ bf16  g_wkt_h[(size_t)DKV * DMODEL];
__device__ bf16  g_wvt_h[(size_t)DKV * DMODEL];
__device__ bf16  g_wot_h[(size_t)DMODEL * DMODEL];
__device__ float g_wgt_t[(size_t)DFF * DMODEL];  // tf32-rounded fp32
__device__ float g_wut_t[(size_t)DFF * DMODEL];
__device__ float g_wdt_t[(size_t)DMODEL * DFF];

// ---------------------------------------------------------------------------
// PTX helpers — baseline sm_80+ only (harness targets plain sm_103)
// ---------------------------------------------------------------------------
__device__ __forceinline__ uint32_t smem_u32(const void* p) {
    uint32_t a;
    asm("{ .reg .u64 t; cvta.to.shared.u64 t, %1; cvt.u32.u64 %0, t; }"
        : "=r"(a) : "l"(p));
    return a;
}

__device__ __forceinline__ void cp16(uint32_t saddr, const void* g) {
    unsigned long long ga = (unsigned long long)__cvta_generic_to_global(g);
    asm volatile("cp.async.cg.shared.global [%0], [%1], 16;\n"
                 :: "r"(saddr), "l"(ga));
}
#define CP_COMMIT() asm volatile("cp.async.commit_group;\n" ::: "memory")
template <int N>
__device__ __forceinline__ void cp_wait() {
    asm volatile("cp.async.wait_group %0;\n" :: "n"(N) : "memory");
}

__device__ __forceinline__ void ldmx4(uint32_t* r, uint32_t addr) {
    asm volatile("ldmatrix.sync.aligned.m8n8.x4.shared.b16 {%0,%1,%2,%3}, [%4];\n"
        : "=r"(r[0]), "=r"(r[1]), "=r"(r[2]), "=r"(r[3]) : "r"(addr));
}

__device__ __forceinline__ void mma16816(float* c, const uint32_t* a, const uint32_t* b) {
    asm volatile(
        "mma.sync.aligned.m16n8k16.row.col.f32.bf16.bf16.f32 "
        "{%0,%1,%2,%3}, {%4,%5,%6,%7}, {%8,%9}, {%0,%1,%2,%3};\n"
        : "+f"(c[0]), "+f"(c[1]), "+f"(c[2]), "+f"(c[3])
        : "r"(a[0]), "r"(a[1]), "r"(a[2]), "r"(a[3]), "r"(b[0]), "r"(b[1]));
}

__device__ __forceinline__ void mma1688t(float* c, const uint32_t* a, const uint32_t* b) {
    asm volatile(
        "mma.sync.aligned.m16n8k8.row.col.f32.tf32.tf32.f32 "
        "{%0,%1,%2,%3}, {%4,%5,%6,%7}, {%8,%9}, {%0,%1,%2,%3};\n"
        : "+f"(c[0]), "+f"(c[1]), "+f"(c[2]), "+f"(c[3])
        : "r"(a[0]), "r"(a[1]), "r"(a[2]), "r"(a[3]), "r"(b[0]), "r"(b[1]));
}

__device__ __forceinline__ float tf32r(float v) {
    uint32_t u;
    asm("cvt.rna.tf32.f32 %0, %1;" : "=r"(u) : "f"(v));
    return __uint_as_float(u);
}

// ===========================================================================
// bf16 GEMM (attention path): C[128x128] = A[M,K] * Bt[N,K]^T (+R)
// 128 threads, warp tile 64x64, BK=32 elems, 3-stage cp.async.
// ===========================================================================
constexpr int LDSS = 80;                 // smem row stride bytes (32 bf16 + pad)
constexpr int MATB = 128 * LDSS;         // 10240

__device__ __forceinline__ void load_stage_b(
    uint32_t sb, int s, const bf16* __restrict__ A, const bf16* __restrict__ B,
    long lda, long ldb, int k0, int tid)
{
    uint32_t base = sb + (uint32_t)(s * 2 * MATB);
    #pragma unroll
    for (int i = 0; i < 4; i++) {
        int idx = tid + i * 128;                 // 0..511
        int r = idx >> 2, cb = (idx & 3) << 4;
        uint32_t so = (uint32_t)(r * LDSS + cb);
        cp16(base + so,        A + (long)r * lda + k0 + (cb >> 1));
        cp16(base + MATB + so, B + (long)r * ldb + k0 + (cb >> 1));
    }
}

__device__ __forceinline__ void compute_stage_b(
    uint32_t sb, int s, int wm, int wn, int l, float acc[4][8][4])
{
    uint32_t As = sb + (uint32_t)(s * 2 * MATB);
    uint32_t Bs = As + MATB;
    uint32_t a_off = (uint32_t)((wm * 64 + (l & 15)) * LDSS + ((l >> 4) << 4));
    uint32_t b_off = (uint32_t)((wn * 64 + ((l >> 4) << 3) + (l & 7)) * LDSS
                                + (((l >> 3) & 1) << 4));
    #pragma unroll
    for (int kk = 0; kk < 2; kk++) {
        uint32_t kb = (uint32_t)(kk * 32);
        uint32_t ah[4][4], bh[8][2];
        #pragma unroll
        for (int m = 0; m < 4; m++)
            ldmx4(ah[m], As + a_off + m * (16 * LDSS) + kb);
        #pragma unroll
        for (int p = 0; p < 4; p++) {
            uint32_t r[4];
            ldmx4(r, Bs + b_off + p * (16 * LDSS) + kb);
            bh[2*p][0] = r[0]; bh[2*p][1] = r[1];
            bh[2*p+1][0] = r[2]; bh[2*p+1][1] = r[3];
        }
        #pragma unroll
        for (int m = 0; m < 4; m++)
            #pragma unroll
            for (int n = 0; n < 8; n++)
                mma16816(acc[m][n], ah[m], bh[n]);
    }
}

template <int OB>
__device__ __forceinline__ void gemm_bf16(
    const bf16* __restrict__ a, long lda, const bf16* __restrict__ b, long ldb,
    const float* __restrict__ R, void* __restrict__ Cv, long ldc,
    int K, int m0, int n0)
{
    constexpr int S = 3;
    extern __shared__ char smem[];
    uint32_t sb = smem_u32(smem);
    const int tid = threadIdx.x, wid = tid >> 5, l = tid & 31;
    const int wm = wid & 1, wn = wid >> 1;

    const bf16* A = a + (long)m0 * lda;
    const bf16* B = b + (long)n0 * ldb;

    float acc[4][8][4];
    #pragma unroll
    for (int m = 0; m < 4; m++)
        #pragma unroll
        for (int n = 0; n < 8; n++)
            #pragma unroll
            for (int i = 0; i < 4; i++) acc[m][n][i] = 0.f;

    const int nk = K >> 5;
    #pragma unroll
    for (int c = 0; c < S - 1; c++) {
        load_stage_b(sb, c, A, B, lda, ldb, c * 32, tid);
        CP_COMMIT();
    }
    int slot_c = 0, slot_p = S - 1;
    for (int c = 0; c < nk; c++) {
        cp_wait<S - 2>();
        __syncthreads();
        if (c + S - 1 < nk)
            load_stage_b(sb, slot_p, A, B, lda, ldb, (c + S - 1) * 32, tid);
        CP_COMMIT();
        compute_stage_b(sb, slot_c, wm, wn, l, acc);
        slot_c = (slot_c + 1 == S) ? 0 : slot_c + 1;
        slot_p = (slot_p + 1 == S) ? 0 : slot_p + 1;
    }

    const int row0 = m0 + wm * 64, col0 = n0 + wn * 64;
    #pragma unroll
    for (int m = 0; m < 4; m++) {
        int r0 = row0 + m * 16 + (l >> 2);
        #pragma unroll
        for (int n = 0; n < 8; n++) {
            int cc = col0 + n * 8 + (l & 3) * 2;
            float2 v0 = make_float2(acc[m][n][0], acc[m][n][1]);
            float2 v1 = make_float2(acc[m][n][2], acc[m][n][3]);
            if (OB == 0) {
                float* C = (float*)Cv;
                if (R) {
                    float2 q0 = *(const float2*)(R + (long)r0 * ldc + cc);
                    float2 q1 = *(const float2*)(R + (long)(r0 + 8) * ldc + cc);
                    v0.x += q0.x; v0.y += q0.y; v1.x += q1.x; v1.y += q1.y;
                }
                *(float2*)(C + (long)r0 * ldc + cc)       = v0;
                *(float2*)(C + (long)(r0 + 8) * ldc + cc) = v1;
            } else {
                bf16* C = (bf16*)Cv;
                __nv_bfloat162 b0, b1;
                b0.x = __float2bfloat16(v0.x); b0.y = __float2bfloat16(v0.y);
                b1.x = __float2bfloat16(v1.x); b1.y = __float2bfloat16(v1.y);
                *(__nv_bfloat162*)(C + (long)r0 * ldc + cc)       = b0;
                *(__nv_bfloat162*)(C + (long)(r0 + 8) * ldc + cc) = b1;
            }
        }
    }
}

constexpr int SM1 = 3 * 2 * MATB;   // 61440

// ===========================================================================
// tf32 GEMM (MLP path): C[128x128] = A[M,K] * Bt[N,K]^T (+R), fp32 in/out.
// Operands pre-rounded to tf32. 128 threads, warp tile 64x64, BK=32 floats,
// 2-stage cp.async, 2 CTAs/SM. ldmatrix.b16 carries fp32 (pair = one float).
// ===========================================================================
constexpr int LDT  = 144;                // smem row stride bytes (32 fp32 + pad)
constexpr int MATT = 128 * LDT;          // 18432

__device__ __forceinline__ void load_stage_t(
    uint32_t sb, int s, const float* __restrict__ A, const float* __restrict__ B,
    long lda, long ldb, int k0, int tid)
{
    uint32_t base = sb + (uint32_t)(s * 2 * MATT);
    #pragma unroll
    for (int i = 0; i < 8; i++) {
        int idx = tid + i * 128;                 // 0..1023
        int r = idx >> 3, cb = (idx & 7) << 4;   // row, byte offset (16B)
        uint32_t so = (uint32_t)(r * LDT + cb);
        cp16(base + so,        A + (long)r * lda + k0 + (cb >> 2));
        cp16(base + MATT + so, B + (long)r * ldb + k0 + (cb >> 2));
    }
}

__device__ __forceinline__ void compute_stage_t(
    uint32_t sb, int s, int wm, int wn, int l, float acc[4][8][4])
{
    uint32_t As = sb + (uint32_t)(s * 2 * MATT);
    uint32_t Bs = As + MATT;
    int g8  = l & 7;
    int hi8 = (l >> 4) << 3;
    int cb  = ((l >> 3) & 1) << 4;
    uint32_t a_base = As + (uint32_t)((wm * 64 + g8 + hi8) * LDT + cb);
    uint32_t b_base = Bs + (uint32_t)((wn * 64 + g8 + hi8) * LDT + cb);
    #pragma unroll
    for (int ks = 0; ks < 4; ks++) {            // 4 k-steps of 8 floats
        uint32_t ko = (uint32_t)(ks * 32);
        uint32_t a[4][4], b[8][2];
        #pragma unroll
        for (int m = 0; m < 4; m++) {
            uint32_t r[4];
            ldmx4(r, a_base + m * (16 * LDT) + ko);
            a[m][0] = r[0]; a[m][1] = r[2]; a[m][2] = r[1]; a[m][3] = r[3];
        }
        #pragma unroll
        for (int p = 0; p < 4; p++) {
            uint32_t r[4];
            ldmx4(r, b_base + p * (16 * LDT) + ko);
            b[2*p][0] = r[0]; b[2*p][1] = r[1];
            b[2*p+1][0] = r[2]; b[2*p+1][1] = r[3];
        }
        #pragma unroll
        for (int m = 0; m < 4; m++)
            #pragma unroll
            for (int n = 0; n < 8; n++)
                mma1688t(acc[m][n], a[m], b[n]);
    }
}

__global__ __launch_bounds__(128, 2) void mma_gemmt_kernel(
    const float* __restrict__ a, long lda, const float* __restrict__ b, long ldb,
    const float* __restrict__ R, float* __restrict__ C, long ldc, int K)
{
    extern __shared__ char smem[];
    uint32_t sb = smem_u32(smem);
    const int tid = threadIdx.x, wid = tid >> 5, l = tid & 31;
    const int wm = wid & 1, wn = wid >> 1;
    const int m0 = blockIdx.y * 128, n0 = blockIdx.x * 128;

    const float* A = a + (long)m0 * lda;
    const float* B = b + (long)n0 * ldb;

    float acc[4][8][4];
    #pragma unroll
    for (int m = 0; m < 4; m++)
        #pragma unroll
        for (int n = 0; n < 8; n++)
            #pragma unroll
            for (int i = 0; i < 4; i++) acc[m][n][i] = 0.f;

    const int nk = K >> 5;
    load_stage_t(sb, 0, A, B, lda, ldb, 0, tid);
    CP_COMMIT();
    int slot_c = 0, slot_p = 1;
    for (int c = 0; c < nk; c++) {
        cp_wait<0>();
        __syncthreads();
        if (c + 1 < nk)
            load_stage_t(sb, slot_p, A, B, lda, ldb, (c + 1) * 32, tid);
        CP_COMMIT();
        compute_stage_t(sb, slot_c, wm, wn, l, acc);
        slot_c ^= 1; slot_p ^= 1;
    }

    const int row0 = m0 + wm * 64, col0 = n0 + wn * 64;
    #pragma unroll
    for (int m = 0; m < 4; m++) {
        int r0 = row0 + m * 16 + (l >> 2);
        #pragma unroll
        for (int n = 0; n < 8; n++) {
            int cc = col0 + n * 8 + (l & 3) * 2;
            float2 v0 = make_float2(acc[m][n][0], acc[m][n][1]);
            float2 v1 = make_float2(acc[m][n][2], acc[m][n][3]);
            if (R) {
                float2 q0 = *(const float2*)(R + (long)r0 * ldc + cc);
                float2 q1 = *(const float2*)(R + (long)(r0 + 8) * ldc + cc);
                v0.x += q0.x; v0.y += q0.y; v1.x += q1.x; v1.y += q1.y;
            }
            *(float2*)(C + (long)r0 * ldc + cc)       = v0;
            *(float2*)(C + (long)(r0 + 8) * ldc + cc) = v1;
        }
    }
}

constexpr int SMT = 2 * 2 * MATT;   // 73728

// ---------------------------------------------------------------------------
// bf16 GEMM wrapper kernels (attention path)
// ---------------------------------------------------------------------------
__global__ __launch_bounds__(128) void mma_gemm1_kernel(
    const bf16* a, long lda, const bf16* b, long ldb,
    const float* R, float* C, long ldc, int K)
{
    gemm_bf16<0>(a, lda, b, ldb, R, C, ldc, K, blockIdx.y * 128, blockIdx.x * 128);
}

__global__ __launch_bounds__(128) void mma_scores_kernel()
{
    int z = blockIdx.z, b = z >> 4, h = z & 15, kh = h >> 1;
    const bf16* A = g_qh + (long)b * SEQ * DMODEL + h * HD;
    const bf16* B = g_kh + (long)b * SEQ * DKV + kh * HD;
    float* C = g_scores + (long)z * SEQ * SEQ;
    gemm_bf16<0>(A, DMODEL, B, DKV, nullptr, C, SEQ, HD,
                 blockIdx.y * 128, blockIdx.x * 128);
}

__global__ __launch_bounds__(128) void mma_pv_kernel()
{
    int z = blockIdx.z, b = z >> 4, h = z & 15, kh = h >> 1;
    const bf16* A = g_ph + (long)z * SEQ * SEQ;
    const bf16* B = g_vth + (long)(b * NKV + kh) * HD * SEQ;
    bf16* C = g_ctxh + (long)b * SEQ * DMODEL + h * HD;
    gemm_bf16<1>(A, SEQ, B, SEQ, nullptr, C, DMODEL, SEQ,
                 blockIdx.y * 128, 0);
}

// ---------------------------------------------------------------------------
// Reductions
// ---------------------------------------------------------------------------
__device__ __forceinline__ float block_reduce_sum(float v)
{
    __shared__ float red[32];
    int lid = threadIdx.x & 31, wid = threadIdx.x >> 5;
    #pragma unroll
    for (int o = 16; o; o >>= 1) v += __shfl_xor_sync(0xffffffffu, v, o);
    if (lid == 0) red[wid] = v;
    __syncthreads();
    v = (threadIdx.x < 8) ? red[threadIdx.x] : 0.f;
    if (wid == 0) {
        #pragma unroll
        for (int o = 4; o; o >>= 1) v += __shfl_xor_sync(0xffffffffu, v, o);
        if (lid == 0) red[0] = v;
    }
    __syncthreads();
    return red[0];
}
__device__ __forceinline__ float block_reduce_max(float v)
{
    __shared__ float red[32];
    int lid = threadIdx.x & 31, wid = threadIdx.x >> 5;
    #pragma unroll
    for (int o = 16; o; o >>= 1) v = fmaxf(v, __shfl_xor_sync(0xffffffffu, v, o));
    if (lid == 0) red[wid] = v;
    __syncthreads();
    v = (threadIdx.x < 8) ? red[threadIdx.x] : -INFINITY;
    if (wid == 0) {
        #pragma unroll
        for (int o = 4; o; o >>= 1) v = fmaxf(v, __shfl_xor_sync(0xffffffffu, v, o));
        if (lid == 0) red[0] = v;
    }
    __syncthreads();
    return red[0];
}

// ---------------------------------------------------------------------------
// RMSNorm -> bf16 (attention input)
// ---------------------------------------------------------------------------
__global__ __launch_bounds__(256) void rmsnorm_bf16_kernel(
    const float* __restrict__ x, const float* __restrict__ w,
    bf16* __restrict__ oh)
{
    long row = blockIdx.x;
    const float* xr = x + row * DMODEL;
    float vals[8];
    float ss = 0.f;
    #pragma unroll
    for (int i = 0; i < 8; i++) {
        int idx = threadIdx.x + i * 256;
        vals[i] = xr[idx];
        ss = fmaf(vals[i], vals[i], ss);
    }
    float total = block_reduce_sum(ss);
    float rstd = rsqrtf(total * (1.0f / DMODEL) + EPSV);
    #pragma unroll
    for (int i = 0; i < 8; i++) {
        int idx = threadIdx.x + i * 256;
        oh[row * DMODEL + idx] = __float2bfloat16(vals[i] * rstd * w[idx]);
    }
}

// RMSNorm -> tf32-rounded fp32 (MLP input)
__global__ __launch_bounds__(256) void rmsnorm_tf32_kernel(
    const float* __restrict__ x, const float* __restrict__ w,
    float* __restrict__ ot)
{
    long row = blockIdx.x;
    const float* xr = x + row * DMODEL;
    float vals[8];
    float ss = 0.f;
    #pragma unroll
    for (int i = 0; i < 8; i++) {
        int idx = threadIdx.x + i * 256;
        vals[i] = xr[idx];
        ss = fmaf(vals[i], vals[i], ss);
    }
    float total = block_reduce_sum(ss);
    float rstd = rsqrtf(total * (1.0f / DMODEL) + EPSV);
    #pragma unroll
    for (int i = 0; i < 8; i++) {
        int idx = threadIdx.x + i * 256;
        ot[row * DMODEL + idx] = tf32r(vals[i] * rstd * w[idx]);
    }
}

// ---------------------------------------------------------------------------
// RoPE (HF-style) fp32 -> bf16
// ---------------------------------------------------------------------------
__global__ __launch_bounds__(64) void rope_kernel(
    const float* __restrict__ x, const float* __restrict__ cs,
    const float* __restrict__ sn, bf16* __restrict__ oh, int ld)
{
    long base = (long)blockIdx.x * ld + blockIdx.y * HD;
    int j = threadIdx.x;
    float e = x[base + 2 * j];
    float o = x[base + 2 * j + 1];
    float c = cs[(long)blockIdx.x * 64 + j];
    float s = sn[(long)blockIdx.x * 64 + j];
    oh[base + j]      = __float2bfloat16(e * c - o * s);
    oh[base + 64 + j] = __float2bfloat16(e * s + o * c);
}

// ---------------------------------------------------------------------------
// Weight transposes: in [RI, CI] fp32 -> out [CI, RI] bf16 or tf32-fp32
// ---------------------------------------------------------------------------
__global__ __launch_bounds__(256) void transpose_bf16_kernel(
    const float* __restrict__ in, bf16* __restrict__ oh, int RI, int CI)
{
    __shared__ float t[32][33];
    int tx = threadIdx.x & 31, ty = threadIdx.x >> 5;
    int r0 = blockIdx.y * 32, c0 = blockIdx.x * 32;
    #pragma unroll
    for (int i = 0; i < 4; i++)
        t[ty + i * 8][tx] = in[(long)(r0 + ty + i * 8) * CI + c0 + tx];
    __syncthreads();
    #pragma unroll
    for (int i = 0; i < 4; i++)
        oh[(long)(c0 + ty + i * 8) * RI + r0 + tx] =
            __float2bfloat16(t[tx][ty + i * 8]);
}

__global__ __launch_bounds__(256) void transpose_tf32_kernel(
    const float* __restrict__ in, float* __restrict__ ot, int RI, int CI)
{
    __shared__ float t[32][33];
    int tx = threadIdx.x & 31, ty = threadIdx.x >> 5;
    int r0 = blockIdx.y * 32, c0 = blockIdx.x * 32;
    #pragma unroll
    for (int i = 0; i < 4; i++)
        t[ty + i * 8][tx] = in[(long)(r0 + ty + i * 8) * CI + c0 + tx];
    __syncthreads();
    #pragma unroll
    for (int i = 0; i < 4; i++)
        ot[(long)(c0 + ty + i * 8) * RI + r0 + tx] = tf32r(t[tx][ty + i * 8]);
}

// V transpose: g_v [b, s, kh*128+d] -> g_vth [(b*8+kh)][d][s] bf16
__global__ __launch_bounds__(256) void vT_kernel()
{
    __shared__ float t[32][33];
    int z = blockIdx.z;
    int b = z >> 3, kh = z & 7;
    const float* in = g_v + (long)b * SEQ * DKV + kh * HD;
    bf16* oh = g_vth + (long)z * HD * SEQ;
    int tx = threadIdx.x & 31, ty = threadIdx.x >> 5;
    int s0 = blockIdx.y * 32, d0 = blockIdx.x * 32;
    #pragma unroll
    for (int i = 0; i < 4; i++)
        t[ty + i * 8][tx] = in[(long)(s0 + ty + i * 8) * DKV + d0 + tx];
    __syncthreads();
    #pragma unroll
    for (int i = 0; i < 4; i++)
        oh[(long)(d0 + ty + i * 8) * SEQ + s0 + tx] =
            __float2bfloat16(t[tx][ty + i * 8]);
}

// ---------------------------------------------------------------------------
// Softmax (scale + mask) -> bf16
// ---------------------------------------------------------------------------
__global__ __launch_bounds__(256) void softmax_kernel(const float* __restrict__ mask)
{
    int z = blockIdx.y;
    int b = z >> 4;
    long row = blockIdx.x;
    const float* srow = g_scores + ((long)z * SEQ + row) * SEQ;
    const float* mrow = mask + ((long)b * SEQ + row) * SEQ;
    bf16* phr = g_ph + ((long)z * SEQ + row) * SEQ;

    float v[8];
    float mx = -INFINITY;
    #pragma unroll
    for (int i = 0; i < 8; i++) {
        int idx = threadIdx.x + i * 256;
        v[i] = fmaf(srow[idx], SM_SCALE, mrow[idx]);
        mx = fmaxf(mx, v[i]);
    }
    float bm = block_reduce_max(mx);
    float sum = 0.f;
    #pragma unroll
    for (int i = 0; i < 8; i++) {
        v[i] = expf(v[i] - bm);
        sum += v[i];
    }
    float total = block_reduce_sum(sum);
    float inv = 1.0f / total;
    #pragma unroll
    for (int i = 0; i < 8; i++) {
        int idx = threadIdx.x + i * 256;
        phr[idx] = __float2bfloat16(v[i] * inv);
    }
}

// ---------------------------------------------------------------------------
// SwiGLU -> tf32-rounded fp32
// ---------------------------------------------------------------------------
__global__ __launch_bounds__(256) void silu_tf32_kernel()
{
    long i = (long)blockIdx.x * 256 + threadIdx.x;
    float g = g_gate[i], u = g_up[i];
    g_mt[i] = tf32r(u * g / (1.0f + expf(-g)));
}

// ---------------------------------------------------------------------------
// Launch
// ---------------------------------------------------------------------------
extern "C" void kernel_launch(void* const* d_in, const int* in_sizes, int n_in,
                              void* d_out, int out_size)
{
    const float* hs   = (const float*)d_in[0];
    const float* cosp = (const float*)d_in[1];
    const float* sinp = (const float*)d_in[2];
    const float* mask = (const float*)d_in[3];
    const float* wq   = (const float*)d_in[4];
    const float* wk   = (const float*)d_in[5];
    const float* wv   = (const float*)d_in[6];
    const float* wo   = (const float*)d_in[7];
    const float* wg   = (const float*)d_in[8];
    const float* wu   = (const float*)d_in[9];
    const float* wd   = (const float*)d_in[10];
    const float* ln1  = (const float*)d_in[11];
    const float* ln2  = (const float*)d_in[12];
    float* out = (float*)d_out;

    cudaFuncSetAttribute(mma_gemm1_kernel,
                         cudaFuncAttributeMaxDynamicSharedMemorySize, SM1);
    cudaFuncSetAttribute(mma_scores_kernel,
                         cudaFuncAttributeMaxDynamicSharedMemorySize, SM1);
    cudaFuncSetAttribute(mma_pv_kernel,
                         cudaFuncAttributeMaxDynamicSharedMemorySize, SM1);
    cudaFuncSetAttribute(mma_gemmt_kernel,
                         cudaFuncAttributeMaxDynamicSharedMemorySize, SMT);

    bf16 *x1h, *qh, *kh, *ctxh;
    bf16 *wqth, *wkth, *wvth, *woth;
    float *wgtt, *wutt, *wdtt;
    float *q, *k, *v, *h2, *x2t, *gate, *up, *mt;
    cudaGetSymbolAddress((void**)&x1h, g_x1h);
    cudaGetSymbolAddress((void**)&qh,  g_qh);
    cudaGetSymbolAddress((void**)&kh,  g_kh);
    cudaGetSymbolAddress((void**)&ctxh,g_ctxh);
    cudaGetSymbolAddress((void**)&wqth,g_wqt_h);
    cudaGetSymbolAddress((void**)&wkth,g_wkt_h);
    cudaGetSymbolAddress((void**)&wvth,g_wvt_h);
    cudaGetSymbolAddress((void**)&woth,g_wot_h);
    cudaGetSymbolAddress((void**)&wgtt,g_wgt_t);
    cudaGetSymbolAddress((void**)&wutt,g_wut_t);
    cudaGetSymbolAddress((void**)&wdtt,g_wdt_t);
    cudaGetSymbolAddress((void**)&q,   g_q);
    cudaGetSymbolAddress((void**)&k,   g_k);
    cudaGetSymbolAddress((void**)&v,   g_v);
    cudaGetSymbolAddress((void**)&h2,  g_h2);
    cudaGetSymbolAddress((void**)&x2t, g_x2t);
    cudaGetSymbolAddress((void**)&gate,g_gate);
    cudaGetSymbolAddress((void**)&up,  g_up);
    cudaGetSymbolAddress((void**)&mt,  g_mt);

    // 1) x1 = rmsnorm(hs) -> bf16
    rmsnorm_bf16_kernel<<<TOK, 256>>>(hs, ln1, x1h);

    // 2) weight transposes: bf16 for attention, tf32-fp32 for MLP
    transpose_bf16_kernel<<<dim3(DMODEL/32, DMODEL/32), 256>>>(wq, wqth, DMODEL, DMODEL);
    transpose_bf16_kernel<<<dim3(DKV/32,    DMODEL/32), 256>>>(wk, wkth, DMODEL, DKV);
    transpose_bf16_kernel<<<dim3(DKV/32,    DMODEL/32), 256>>>(wv, wvth, DMODEL, DKV);
    transpose_bf16_kernel<<<dim3(DMODEL/32, DMODEL/32), 256>>>(wo, woth, DMODEL, DMODEL);
    transpose_tf32_kernel<<<dim3(DFF/32,    DMODEL/32), 256>>>(wg, wgtt, DMODEL, DFF);
    transpose_tf32_kernel<<<dim3(DFF/32,    DMODEL/32), 256>>>(wu, wutt, DMODEL, DFF);
    transpose_tf32_kernel<<<dim3(DMODEL/32, DFF/32),    256>>>(wd, wdtt, DFF, DMODEL);

    // 3) QKV projections (bf16, fp32 out)
    mma_gemm1_kernel<<<dim3(DMODEL/128, TOK/128), 128, SM1>>>(
        x1h, DMODEL, wqth, DMODEL, nullptr, q, DMODEL, DMODEL);
    mma_gemm1_kernel<<<dim3(DKV/128, TOK/128), 128, SM1>>>(
        x1h, DMODEL, wkth, DMODEL, nullptr, k, DKV, DMODEL);
    mma_gemm1_kernel<<<dim3(DKV/128, TOK/128), 128, SM1>>>(
        x1h, DMODEL, wvth, DMODEL, nullptr, v, DKV, DMODEL);

    // 4) RoPE -> bf16; V transpose -> bf16
    rope_kernel<<<dim3(TOK, NHEADS), 64>>>(q, cosp, sinp, qh, DMODEL);
    rope_kernel<<<dim3(TOK, NKV),    64>>>(k, cosp, sinp, kh, DKV);
    vT_kernel<<<dim3(HD/32, SEQ/32, BATCH*NKV), 256>>>();

    // 5) scores = Q K^T
    mma_scores_kernel<<<dim3(SEQ/128, SEQ/128, BATCH*NHEADS), 128, SM1>>>();

    // 6) softmax -> P bf16
    softmax_kernel<<<dim3(SEQ, BATCH*NHEADS), 256>>>(mask);

    // 7) ctx = P V (writes bf16 directly)
    mma_pv_kernel<<<dim3(1, SEQ/128, BATCH*NHEADS), 128, SM1>>>();

    // 8) h2 = hs + ctx @ wo
    mma_gemm1_kernel<<<dim3(DMODEL/128, TOK/128), 128, SM1>>>(
        ctxh, DMODEL, woth, DMODEL, hs, h2, DMODEL, DMODEL);

    // 9) x2 = rmsnorm(h2) -> tf32-rounded fp32
    rmsnorm_tf32_kernel<<<TOK, 256>>>(h2, ln2, x2t);

    // 10) MLP (tf32)
    mma_gemmt_kernel<<<dim3(DFF/128, TOK/128), 128, SMT>>>(
        x2t, DMODEL, wgtt, DMODEL, nullptr, gate, DFF, DMODEL);
    mma_gemmt_kernel<<<dim3(DFF/128, TOK/128), 128, SMT>>>(
        x2t, DMODEL, wutt, DMODEL, nullptr, up, DFF, DMODEL);
    silu_tf32_kernel<<<(unsigned)((long)TOK*DFF/256), 256>>>();

    // 11) out = h2 + (silu(gate)*up) @ wd  (tf32)
    mma_gemmt_kernel<<<dim3(DMODEL/128, TOK/128), 128, SMT>>>(
        mt, DFF, wdtt, DFF, h2, out, DMODEL, DFF);
}

// round 8
// speedup vs baseline: 5.3737x; 1.6358x over previous
#include <cuda_runtime.h>
#include <cuda_fp16.h>
#include <math.h>
#include <stdint.h>

// ---------------------------------------------------------------------------
// Problem constants
// ---------------------------------------------------------------------------
constexpr int BATCH   = 2;
constexpr int SEQ     = 2048;
constexpr int DMODEL  = 2048;
constexpr int DFF     = 8192;
constexpr int NHEADS  = 16;
constexpr int NKV     = 8;
constexpr int HD      = 128;
constexpr int DKV     = NKV * HD;      // 1024
constexpr int TOK     = BATCH * SEQ;   // 4096
constexpr float EPSV  = 1e-5f;
constexpr float SM_SCALE = 0.08838834764831845f; // 128^-0.5

typedef __half f16;

// ---------------------------------------------------------------------------
// Scratch (device globals; allocation anywhere is forbidden)
// ---------------------------------------------------------------------------
__device__ f16   g_x1h [(size_t)TOK * DMODEL];
__device__ f16   g_qh  [(size_t)TOK * DMODEL];   // rope'd Q (fp16)
__device__ f16   g_kh  [(size_t)TOK * DKV];      // rope'd K (fp16)
__device__ float g_v   [(size_t)TOK * DKV];
__device__ f16   g_vth [(size_t)TOK * DKV];      // V^T: [(b*8+kh)][128][SEQ]
__device__ f16   g_sc  [(size_t)BATCH * NHEADS * SEQ * SEQ];  // 268 MB
__device__ f16   g_ph  [(size_t)BATCH * NHEADS * SEQ * SEQ];
__device__ f16   g_ctxh[(size_t)TOK * DMODEL];
__device__ float g_h2  [(size_t)TOK * DMODEL];
__device__ f16   g_x2h [(size_t)TOK * DMODEL];
__device__ f16   g_g16 [(size_t)TOK * DFF];
__device__ f16   g_u16 [(size_t)TOK * DFF];
__device__ f16   g_mh  [(size_t)TOK * DFF];
// transposed fp16 weights: [N, K]
__device__ f16   g_wqt[(size_t)DMODEL * DMODEL];
__device__ f16   g_wkt[(size_t)DKV * DMODEL];
__device__ f16   g_wvt[(size_t)DKV * DMODEL];
__device__ f16   g_wot[(size_t)DMODEL * DMODEL];
__device__ f16   g_wgt[(size_t)DFF * DMODEL];
__device__ f16   g_wut[(size_t)DFF * DMODEL];
__device__ f16   g_wdt[(size_t)DMODEL * DFF];

// ---------------------------------------------------------------------------
// PTX helpers — baseline sm_80+ only (harness targets plain sm_103)
// ---------------------------------------------------------------------------
__device__ __forceinline__ uint32_t smem_u32(const void* p) {
    uint32_t a;
    asm("{ .reg .u64 t; cvta.to.shared.u64 t, %1; cvt.u32.u64 %0, t; }"
        : "=r"(a) : "l"(p));
    return a;
}

__device__ __forceinline__ void cp16(uint32_t saddr, const void* g) {
    unsigned long long ga = (unsigned long long)__cvta_generic_to_global(g);
    asm volatile("cp.async.cg.shared.global [%0], [%1], 16;\n"
                 :: "r"(saddr), "l"(ga));
}
#define CP_COMMIT() asm volatile("cp.async.commit_group;\n" ::: "memory")
template <int N>
__device__ __forceinline__ void cp_wait() {
    asm volatile("cp.async.wait_group %0;\n" :: "n"(N) : "memory");
}

__device__ __forceinline__ void ldmx4(uint32_t* r, uint32_t addr) {
    asm volatile("ldmatrix.sync.aligned.m8n8.x4.shared.b16 {%0,%1,%2,%3}, [%4];\n"
        : "=r"(r[0]), "=r"(r[1]), "=r"(r[2]), "=r"(r[3]) : "r"(addr));
}

__device__ __forceinline__ void mma16816h(float* c, const uint32_t* a, const uint32_t* b) {
    asm volatile(
        "mma.sync.aligned.m16n8k16.row.col.f32.f16.f16.f32 "
        "{%0,%1,%2,%3}, {%4,%5,%6,%7}, {%8,%9}, {%0,%1,%2,%3};\n"
        : "+f"(c[0]), "+f"(c[1]), "+f"(c[2]), "+f"(c[3])
        : "r"(a[0]), "r"(a[1]), "r"(a[2]), "r"(a[3]), "r"(b[0]), "r"(b[1]));
}

// ===========================================================================
// fp16 GEMM: C[128x128] tile of A[M,K] * Bt[N,K]^T (+R)
// 128 threads, warp tile 64x64, BK=32 elems, 3-stage cp.async.
// OB=0: fp32 out (+residual). OB=1: fp16 out. OB=2: fp16 out + fused RoPE.
// ===========================================================================
constexpr int LDSS = 80;                 // smem row stride bytes (32 f16 + pad)
constexpr int MATB = 128 * LDSS;         // 10240

__device__ __forceinline__ void load_stage_h(
    uint32_t sb, int s, const f16* __restrict__ A, const f16* __restrict__ B,
    long lda, long ldb, int k0, int tid)
{
    uint32_t base = sb + (uint32_t)(s * 2 * MATB);
    #pragma unroll
    for (int i = 0; i < 4; i++) {
        int idx = tid + i * 128;                 // 0..511
        int r = idx >> 2, cb = (idx & 3) << 4;
        uint32_t so = (uint32_t)(r * LDSS + cb);
        cp16(base + so,        A + (long)r * lda + k0 + (cb >> 1));
        cp16(base + MATB + so, B + (long)r * ldb + k0 + (cb >> 1));
    }
}

__device__ __forceinline__ void compute_stage_h(
    uint32_t sb, int s, int wm, int wn, int l, float acc[4][8][4])
{
    uint32_t As = sb + (uint32_t)(s * 2 * MATB);
    uint32_t Bs = As + MATB;
    uint32_t a_off = (uint32_t)((wm * 64 + (l & 15)) * LDSS + ((l >> 4) << 4));
    uint32_t b_off = (uint32_t)((wn * 64 + ((l >> 4) << 3) + (l & 7)) * LDSS
                                + (((l >> 3) & 1) << 4));
    #pragma unroll
    for (int kk = 0; kk < 2; kk++) {
        uint32_t kb = (uint32_t)(kk * 32);
        uint32_t ah[4][4], bh[8][2];
        #pragma unroll
        for (int m = 0; m < 4; m++)
            ldmx4(ah[m], As + a_off + m * (16 * LDSS) + kb);
        #pragma unroll
        for (int p = 0; p < 4; p++) {
            uint32_t r[4];
            ldmx4(r, Bs + b_off + p * (16 * LDSS) + kb);
            bh[2*p][0] = r[0]; bh[2*p][1] = r[1];
            bh[2*p+1][0] = r[2]; bh[2*p+1][1] = r[3];
        }
        #pragma unroll
        for (int m = 0; m < 4; m++)
            #pragma unroll
            for (int n = 0; n < 8; n++)
                mma16816h(acc[m][n], ah[m], bh[n]);
    }
}

template <int OB>
__device__ __forceinline__ void gemm_f16(
    const f16* __restrict__ a, long lda, const f16* __restrict__ b, long ldb,
    const float* __restrict__ R, void* __restrict__ Cv, long ldc,
    int K, int m0, int n0,
    const float* __restrict__ cs, const float* __restrict__ sn)
{
    constexpr int S = 3;
    extern __shared__ char smem[];
    uint32_t sb = smem_u32(smem);
    const int tid = threadIdx.x, wid = tid >> 5, l = tid & 31;
    const int wm = wid & 1, wn = wid >> 1;

    const f16* A = a + (long)m0 * lda;
    const f16* B = b + (long)n0 * ldb;

    float acc[4][8][4];
    #pragma unroll
    for (int m = 0; m < 4; m++)
        #pragma unroll
        for (int n = 0; n < 8; n++)
            #pragma unroll
            for (int i = 0; i < 4; i++) acc[m][n][i] = 0.f;

    const int nk = K >> 5;
    #pragma unroll
    for (int c = 0; c < S - 1; c++) {
        load_stage_h(sb, c, A, B, lda, ldb, c * 32, tid);
        CP_COMMIT();
    }
    int slot_c = 0, slot_p = S - 1;
    for (int c = 0; c < nk; c++) {
        cp_wait<S - 2>();
        __syncthreads();
        if (c + S - 1 < nk)
            load_stage_h(sb, slot_p, A, B, lda, ldb, (c + S - 1) * 32, tid);
        CP_COMMIT();
        compute_stage_h(sb, slot_c, wm, wn, l, acc);
        slot_c = (slot_c + 1 == S) ? 0 : slot_c + 1;
        slot_p = (slot_p + 1 == S) ? 0 : slot_p + 1;
    }

    const int row0 = m0 + wm * 64, col0 = n0 + wn * 64;
    #pragma unroll
    for (int m = 0; m < 4; m++) {
        int r0 = row0 + m * 16 + (l >> 2);
        #pragma unroll
        for (int n = 0; n < 8; n++) {
            int cc = col0 + n * 8 + (l & 3) * 2;   // even global column
            float2 v0 = make_float2(acc[m][n][0], acc[m][n][1]);
            float2 v1 = make_float2(acc[m][n][2], acc[m][n][3]);
            if (OB == 0) {
                float* C = (float*)Cv;
                if (R) {
                    float2 q0 = *(const float2*)(R + (long)r0 * ldc + cc);
                    float2 q1 = *(const float2*)(R + (long)(r0 + 8) * ldc + cc);
                    v0.x += q0.x; v0.y += q0.y; v1.x += q1.x; v1.y += q1.y;
                }
                *(float2*)(C + (long)r0 * ldc + cc)       = v0;
                *(float2*)(C + (long)(r0 + 8) * ldc + cc) = v1;
            } else if (OB == 1) {
                f16* C = (f16*)Cv;
                __half2 h0, h1;
                h0.x = __float2half(v0.x); h0.y = __float2half(v0.y);
                h1.x = __float2half(v1.x); h1.y = __float2half(v1.y);
                *(__half2*)(C + (long)r0 * ldc + cc)       = h0;
                *(__half2*)(C + (long)(r0 + 8) * ldc + cc) = h1;
            } else {
                // OB == 2: fused RoPE. cc even; pair (x[2j], x[2j+1]) of head.
                f16* C = (f16*)Cv;
                int hb = cc & ~127;          // head base column
                int j  = (cc & 127) >> 1;    // rotary index 0..63
                float c0 = cs[(long)r0 * 64 + j];
                float s0 = sn[(long)r0 * 64 + j];
                C[(long)r0 * ldc + hb + j]      = __float2half(v0.x * c0 - v0.y * s0);
                C[(long)r0 * ldc + hb + 64 + j] = __float2half(v0.x * s0 + v0.y * c0);
                float c1 = cs[(long)(r0 + 8) * 64 + j];
                float s1 = sn[(long)(r0 + 8) * 64 + j];
                C[(long)(r0 + 8) * ldc + hb + j]      = __float2half(v1.x * c1 - v1.y * s1);
                C[(long)(r0 + 8) * ldc + hb + 64 + j] = __float2half(v1.x * s1 + v1.y * c1);
            }
        }
    }
}

constexpr int SM1 = 3 * 2 * MATB;   // 61440

// ---------------------------------------------------------------------------
// GEMM wrapper kernels
// ---------------------------------------------------------------------------
__global__ __launch_bounds__(128) void gemm_f32out_kernel(
    const f16* a, long lda, const f16* b, long ldb,
    const float* R, float* C, long ldc, int K)
{
    gemm_f16<0>(a, lda, b, ldb, R, C, ldc, K,
                blockIdx.y * 128, blockIdx.x * 128, nullptr, nullptr);
}

__global__ __launch_bounds__(128) void gemm_f16out_kernel(
    const f16* a, long lda, const f16* b, long ldb,
    f16* C, long ldc, int K)
{
    gemm_f16<1>(a, lda, b, ldb, nullptr, C, ldc, K,
                blockIdx.y * 128, blockIdx.x * 128, nullptr, nullptr);
}

__global__ __launch_bounds__(128) void gemm_rope_kernel(
    const f16* a, long lda, const f16* b, long ldb,
    f16* C, long ldc, int K, const float* cs, const float* sn)
{
    gemm_f16<2>(a, lda, b, ldb, nullptr, C, ldc, K,
                blockIdx.y * 128, blockIdx.x * 128, cs, sn);
}

__global__ __launch_bounds__(128) void gemm_scores_kernel()
{
    int z = blockIdx.z, b = z >> 4, h = z & 15, kh = h >> 1;
    const f16* A = g_qh + (long)b * SEQ * DMODEL + h * HD;
    const f16* B = g_kh + (long)b * SEQ * DKV + kh * HD;
    f16* C = g_sc + (long)z * SEQ * SEQ;
    gemm_f16<1>(A, DMODEL, B, DKV, nullptr, C, SEQ, HD,
                blockIdx.y * 128, blockIdx.x * 128, nullptr, nullptr);
}

__global__ __launch_bounds__(128) void gemm_pv_kernel()
{
    int z = blockIdx.z, b = z >> 4, h = z & 15, kh = h >> 1;
    const f16* A = g_ph + (long)z * SEQ * SEQ;
    const f16* B = g_vth + (long)(b * NKV + kh) * HD * SEQ;
    f16* C = g_ctxh + (long)b * SEQ * DMODEL + h * HD;
    gemm_f16<1>(A, SEQ, B, SEQ, nullptr, C, DMODEL, SEQ,
                blockIdx.y * 128, 0, nullptr, nullptr);
}

// ---------------------------------------------------------------------------
// Reductions
// ---------------------------------------------------------------------------
__device__ __forceinline__ float block_reduce_sum(float v)
{
    __shared__ float red[32];
    int lid = threadIdx.x & 31, wid = threadIdx.x >> 5;
    #pragma unroll
    for (int o = 16; o; o >>= 1) v += __shfl_xor_sync(0xffffffffu, v, o);
    if (lid == 0) red[wid] = v;
    __syncthreads();
    v = (threadIdx.x < 8) ? red[threadIdx.x] : 0.f;
    if (wid == 0) {
        #pragma unroll
        for (int o = 4; o; o >>= 1) v += __shfl_xor_sync(0xffffffffu, v, o);
        if (lid == 0) red[0] = v;
    }
    __syncthreads();
    return red[0];
}
__device__ __forceinline__ float block_reduce_max(float v)
{
    __shared__ float red[32];
    int lid = threadIdx.x & 31, wid = threadIdx.x >> 5;
    #pragma unroll
    for (int o = 16; o; o >>= 1) v = fmaxf(v, __shfl_xor_sync(0xffffffffu, v, o));
    if (lid == 0) red[wid] = v;
    __syncthreads();
    v = (threadIdx.x < 8) ? red[threadIdx.x] : -INFINITY;
    if (wid == 0) {
        #pragma unroll
        for (int o = 4; o; o >>= 1) v = fmaxf(v, __shfl_xor_sync(0xffffffffu, v, o));
        if (lid == 0) red[0] = v;
    }
    __syncthreads();
    return red[0];
}

// ---------------------------------------------------------------------------
// RMSNorm -> fp16
// ---------------------------------------------------------------------------
__global__ __launch_bounds__(256) void rmsnorm_f16_kernel(
    const float* __restrict__ x, const float* __restrict__ w,
    f16* __restrict__ oh)
{
    long row = blockIdx.x;
    const float* xr = x + row * DMODEL;
    float vals[8];
    float ss = 0.f;
    #pragma unroll
    for (int i = 0; i < 8; i++) {
        int idx = threadIdx.x + i * 256;
        vals[i] = xr[idx];
        ss = fmaf(vals[i], vals[i], ss);
    }
    float total = block_reduce_sum(ss);
    float rstd = rsqrtf(total * (1.0f / DMODEL) + EPSV);
    #pragma unroll
    for (int i = 0; i < 8; i++) {
        int idx = threadIdx.x + i * 256;
        oh[row * DMODEL + idx] = __float2half(vals[i] * rstd * w[idx]);
    }
}

// ---------------------------------------------------------------------------
// Weight transpose: in [RI, CI] fp32 -> out [CI, RI] fp16
// ---------------------------------------------------------------------------
__global__ __launch_bounds__(256) void transpose_f16_kernel(
    const float* __restrict__ in, f16* __restrict__ oh, int RI, int CI)
{
    __shared__ float t[32][33];
    int tx = threadIdx.x & 31, ty = threadIdx.x >> 5;
    int r0 = blockIdx.y * 32, c0 = blockIdx.x * 32;
    #pragma unroll
    for (int i = 0; i < 4; i++)
        t[ty + i * 8][tx] = in[(long)(r0 + ty + i * 8) * CI + c0 + tx];
    __syncthreads();
    #pragma unroll
    for (int i = 0; i < 4; i++)
        oh[(long)(c0 + ty + i * 8) * RI + r0 + tx] =
            __float2half(t[tx][ty + i * 8]);
}

// V transpose: g_v [b, s, kh*128+d] -> g_vth [(b*8+kh)][d][s] fp16
__global__ __launch_bounds__(256) void vT_kernel()
{
    __shared__ float t[32][33];
    int z = blockIdx.z;
    int b = z >> 3, kh = z & 7;
    const float* in = g_v + (long)b * SEQ * DKV + kh * HD;
    f16* oh = g_vth + (long)z * HD * SEQ;
    int tx = threadIdx.x & 31, ty = threadIdx.x >> 5;
    int s0 = blockIdx.y * 32, d0 = blockIdx.x * 32;
    #pragma unroll
    for (int i = 0; i < 4; i++)
        t[ty + i * 8][tx] = in[(long)(s0 + ty + i * 8) * DKV + d0 + tx];
    __syncthreads();
    #pragma unroll
    for (int i = 0; i < 4; i++)
        oh[(long)(d0 + ty + i * 8) * SEQ + s0 + tx] =
            __float2half(t[tx][ty + i * 8]);
}

// ---------------------------------------------------------------------------
// Softmax (scale + mask), fp16 in -> fp16 out
// ---------------------------------------------------------------------------
__global__ __launch_bounds__(256) void softmax_kernel(const float* __restrict__ mask)
{
    int z = blockIdx.y;
    int b = z >> 4;
    long row = blockIdx.x;
    const f16* srow = g_sc + ((long)z * SEQ + row) * SEQ;
    const float* mrow = mask + ((long)b * SEQ + row) * SEQ;
    f16* phr = g_ph + ((long)z * SEQ + row) * SEQ;

    float v[8];
    float mx = -INFINITY;
    #pragma unroll
    for (int i = 0; i < 8; i++) {
        int idx = threadIdx.x + i * 256;
        v[i] = fmaf(__half2float(srow[idx]), SM_SCALE, mrow[idx]);
        mx = fmaxf(mx, v[i]);
    }
    float bm = block_reduce_max(mx);
    float sum = 0.f;
    #pragma unroll
    for (int i = 0; i < 8; i++) {
        v[i] = expf(v[i] - bm);
        sum += v[i];
    }
    float total = block_reduce_sum(sum);
    float inv = 1.0f / total;
    #pragma unroll
    for (int i = 0; i < 8; i++) {
        int idx = threadIdx.x + i * 256;
        phr[idx] = __float2half(v[i] * inv);
    }
}

// ---------------------------------------------------------------------------
// SwiGLU: mh = silu(gate) * up  (fp16 in/out)
// ---------------------------------------------------------------------------
__global__ __launch_bounds__(256) void silu_kernel()
{
    long i = (long)blockIdx.x * 256 + threadIdx.x;
    float g = __half2float(g_g16[i]);
    float u = __half2float(g_u16[i]);
    g_mh[i] = __float2half(u * g / (1.0f + expf(-g)));
}

// ---------------------------------------------------------------------------
// Launch
// ---------------------------------------------------------------------------
extern "C" void kernel_launch(void* const* d_in, const int* in_sizes, int n_in,
                              void* d_out, int out_size)
{
    const float* hs   = (const float*)d_in[0];
    const float* cosp = (const float*)d_in[1];
    const float* sinp = (const float*)d_in[2];
    const float* mask = (const float*)d_in[3];
    const float* wq   = (const float*)d_in[4];
    const float* wk   = (const float*)d_in[5];
    const float* wv   = (const float*)d_in[6];
    const float* wo   = (const float*)d_in[7];
    const float* wg   = (const float*)d_in[8];
    const float* wu   = (const float*)d_in[9];
    const float* wd   = (const float*)d_in[10];
    const float* ln1  = (const float*)d_in[11];
    const float* ln2  = (const float*)d_in[12];
    float* out = (float*)d_out;

    cudaFuncSetAttribute(gemm_f32out_kernel,
                         cudaFuncAttributeMaxDynamicSharedMemorySize, SM1);
    cudaFuncSetAttribute(gemm_f16out_kernel,
                         cudaFuncAttributeMaxDynamicSharedMemorySize, SM1);
    cudaFuncSetAttribute(gemm_rope_kernel,
                         cudaFuncAttributeMaxDynamicSharedMemorySize, SM1);
    cudaFuncSetAttribute(gemm_scores_kernel,
                         cudaFuncAttributeMaxDynamicSharedMemorySize, SM1);
    cudaFuncSetAttribute(gemm_pv_kernel,
                         cudaFuncAttributeMaxDynamicSharedMemorySize, SM1);

    f16 *x1h, *qh, *kh, *vth, *ctxh, *x2h, *g16, *u16, *mh;
    f16 *wqt, *wkt, *wvt, *wot, *wgt, *wut, *wdt;
    float *v, *h2;
    cudaGetSymbolAddress((void**)&x1h, g_x1h);
    cudaGetSymbolAddress((void**)&qh,  g_qh);
    cudaGetSymbolAddress((void**)&kh,  g_kh);
    cudaGetSymbolAddress((void**)&vth, g_vth);
    cudaGetSymbolAddress((void**)&ctxh,g_ctxh);
    cudaGetSymbolAddress((void**)&x2h, g_x2h);
    cudaGetSymbolAddress((void**)&g16, g_g16);
    cudaGetSymbolAddress((void**)&u16, g_u16);
    cudaGetSymbolAddress((void**)&mh,  g_mh);
    cudaGetSymbolAddress((void**)&wqt, g_wqt);
    cudaGetSymbolAddress((void**)&wkt, g_wkt);
    cudaGetSymbolAddress((void**)&wvt, g_wvt);
    cudaGetSymbolAddress((void**)&wot, g_wot);
    cudaGetSymbolAddress((void**)&wgt, g_wgt);
    cudaGetSymbolAddress((void**)&wut, g_wut);
    cudaGetSymbolAddress((void**)&wdt, g_wdt);
    cudaGetSymbolAddress((void**)&v,   g_v);
    cudaGetSymbolAddress((void**)&h2,  g_h2);

    // 1) x1 = rmsnorm(hs) -> fp16
    rmsnorm_f16_kernel<<<TOK, 256>>>(hs, ln1, x1h);

    // 2) weight transposes -> fp16 [N,K]
    transpose_f16_kernel<<<dim3(DMODEL/32, DMODEL/32), 256>>>(wq, wqt, DMODEL, DMODEL);
    transpose_f16_kernel<<<dim3(DKV/32,    DMODEL/32), 256>>>(wk, wkt, DMODEL, DKV);
    transpose_f16_kernel<<<dim3(DKV/32,    DMODEL/32), 256>>>(wv, wvt, DMODEL, DKV);
    transpose_f16_kernel<<<dim3(DMODEL/32, DMODEL/32), 256>>>(wo, wot, DMODEL, DMODEL);
    transpose_f16_kernel<<<dim3(DFF/32,    DMODEL/32), 256>>>(wg, wgt, DMODEL, DFF);
    transpose_f16_kernel<<<dim3(DFF/32,    DMODEL/32), 256>>>(wu, wut, DMODEL, DFF);
    transpose_f16_kernel<<<dim3(DMODEL/32, DFF/32),    256>>>(wd, wdt, DFF, DMODEL);

    // 3) Q/K projections with fused RoPE -> fp16; V projection -> fp32
    gemm_rope_kernel<<<dim3(DMODEL/128, TOK/128), 128, SM1>>>(
        x1h, DMODEL, wqt, DMODEL, qh, DMODEL, DMODEL, cosp, sinp);
    gemm_rope_kernel<<<dim3(DKV/128, TOK/128), 128, SM1>>>(
        x1h, DMODEL, wkt, DMODEL, kh, DKV, DMODEL, cosp, sinp);
    gemm_f32out_kernel<<<dim3(DKV/128, TOK/128), 128, SM1>>>(
        x1h, DMODEL, wvt, DMODEL, nullptr, v, DKV, DMODEL);

    // 4) V transpose -> fp16
    vT_kernel<<<dim3(HD/32, SEQ/32, BATCH*NKV), 256>>>();

    // 5) scores = Q K^T -> fp16
    gemm_scores_kernel<<<dim3(SEQ/128, SEQ/128, BATCH*NHEADS), 128, SM1>>>();

    // 6) softmax -> P fp16
    softmax_kernel<<<dim3(SEQ, BATCH*NHEADS), 256>>>(mask);

    // 7) ctx = P V -> fp16
    gemm_pv_kernel<<<dim3(1, SEQ/128, BATCH*NHEADS), 128, SM1>>>();

    // 8) h2 = hs + ctx @ wo
    gemm_f32out_kernel<<<dim3(DMODEL/128, TOK/128), 128, SM1>>>(
        ctxh, DMODEL, wot, DMODEL, hs, h2, DMODEL, DMODEL);

    // 9) x2 = rmsnorm(h2) -> fp16
    rmsnorm_f16_kernel<<<TOK, 256>>>(h2, ln2, x2h);

    // 10) MLP (fp16)
    gemm_f16out_kernel<<<dim3(DFF/128, TOK/128), 128, SM1>>>(
        x2h, DMODEL, wgt, DMODEL, g16, DFF, DMODEL);
    gemm_f16out_kernel<<<dim3(DFF/128, TOK/128), 128, SM1>>>(
        x2h, DMODEL, wut, DMODEL, u16, DFF, DMODEL);
    silu_kernel<<<(unsigned)((long)TOK*DFF/256), 256>>>();

    // 11) out = h2 + m @ wd
    gemm_f32out_kernel<<<dim3(DMODEL/128, TOK/128), 128, SM1>>>(
        mh, DFF, wdt, DFF, h2, out, DMODEL, DFF);
}

// round 10
// speedup vs baseline: 5.4647x; 1.0169x over previous
#include <cuda_runtime.h>
#include <cuda_fp16.h>
#include <math.h>
#include <stdint.h>

// ---------------------------------------------------------------------------
// Problem constants
// ---------------------------------------------------------------------------
constexpr int BATCH   = 2;
constexpr int SEQ     = 2048;
constexpr int DMODEL  = 2048;
constexpr int DFF     = 8192;
constexpr int NHEADS  = 16;
constexpr int NKV     = 8;
constexpr int HD      = 128;
constexpr int DKV     = NKV * HD;      // 1024
constexpr int TOK     = BATCH * SEQ;   // 4096
constexpr float EPSV  = 1e-5f;
constexpr float SM_SCALE = 0.08838834764831845f; // 128^-0.5

typedef __half f16;

// ---------------------------------------------------------------------------
// Scratch (device globals; allocation anywhere is forbidden)
// ---------------------------------------------------------------------------
__device__ f16   g_x1h [(size_t)TOK * DMODEL];
__device__ f16   g_qh  [(size_t)TOK * DMODEL];   // rope'd Q (fp16)
__device__ f16   g_kh  [(size_t)TOK * DKV];      // rope'd K (fp16)
__device__ float g_v   [(size_t)TOK * DKV];
__device__ f16   g_vth [(size_t)TOK * DKV];      // V^T: [(b*8+kh)][128][SEQ]
__device__ f16   g_sc  [(size_t)BATCH * NHEADS * SEQ * SEQ];  // 268 MB
__device__ f16   g_ph  [(size_t)BATCH * NHEADS * SEQ * SEQ];
__device__ f16   g_ctxh[(size_t)TOK * DMODEL];
__device__ float g_h2  [(size_t)TOK * DMODEL];
__device__ f16   g_x2h [(size_t)TOK * DMODEL];
__device__ f16   g_g16 [(size_t)TOK * DFF];
__device__ f16   g_mh  [(size_t)TOK * DFF];
// transposed fp16 weights: [N, K]
__device__ f16   g_wqt[(size_t)DMODEL * DMODEL];
__device__ f16   g_wkt[(size_t)DKV * DMODEL];
__device__ f16   g_wvt[(size_t)DKV * DMODEL];
__device__ f16   g_wot[(size_t)DMODEL * DMODEL];
__device__ f16   g_wgt[(size_t)DFF * DMODEL];
__device__ f16   g_wut[(size_t)DFF * DMODEL];
__device__ f16   g_wdt[(size_t)DMODEL * DFF];

// ---------------------------------------------------------------------------
// PTX helpers — baseline sm_80+ only (harness targets plain sm_103)
// ---------------------------------------------------------------------------
__device__ __forceinline__ uint32_t smem_u32(const void* p) {
    uint32_t a;
    asm("{ .reg .u64 t; cvta.to.shared.u64 t, %1; cvt.u32.u64 %0, t; }"
        : "=r"(a) : "l"(p));
    return a;
}

__device__ __forceinline__ void cp16(uint32_t saddr, const void* g) {
    unsigned long long ga = (unsigned long long)__cvta_generic_to_global(g);
    asm volatile("cp.async.cg.shared.global [%0], [%1], 16;\n"
                 :: "r"(saddr), "l"(ga));
}
#define CP_COMMIT() asm volatile("cp.async.commit_group;\n" ::: "memory")
template <int N>
__device__ __forceinline__ void cp_wait() {
    asm volatile("cp.async.wait_group %0;\n" :: "n"(N) : "memory");
}

__device__ __forceinline__ void ldmx4(uint32_t* r, uint32_t addr) {
    asm volatile("ldmatrix.sync.aligned.m8n8.x4.shared.b16 {%0,%1,%2,%3}, [%4];\n"
        : "=r"(r[0]), "=r"(r[1]), "=r"(r[2]), "=r"(r[3]) : "r"(addr));
}

__device__ __forceinline__ void mma16816h(float* c, const uint32_t* a, const uint32_t* b) {
    asm volatile(
        "mma.sync.aligned.m16n8k16.row.col.f32.f16.f16.f32 "
        "{%0,%1,%2,%3}, {%4,%5,%6,%7}, {%8,%9}, {%0,%1,%2,%3};\n"
        : "+f"(c[0]), "+f"(c[1]), "+f"(c[2]), "+f"(c[3])
        : "r"(a[0]), "r"(a[1]), "r"(a[2]), "r"(a[3]), "r"(b[0]), "r"(b[1]));
}

constexpr int LDSS = 80;                 // smem row stride bytes (32 f16 + pad)

// ===========================================================================
// 256-thread fp16 GEMM: C[128 x 256] tile of A[M,K] * Bt[N,K]^T (+R)
// 8 warps in 2x4, warp tile 64x64, BK=32, 3-stage cp.async, 1 CTA/SM.
// OB=0: fp32 out (+residual). OB=1: fp16 out. OB=2: fp16 + fused RoPE.
// OB=3: fp16 out = silu(G) * result (fused SwiGLU).
// ===========================================================================
constexpr int AB2   = 128 * LDSS;        // 10240
constexpr int BB2   = 256 * LDSS;        // 20480
constexpr int STG2  = AB2 + BB2;         // 30720
constexpr int SM2   = 3 * STG2;          // 92160

__device__ __forceinline__ void load_stage_2(
    uint32_t sb, int s, const f16* __restrict__ A, const f16* __restrict__ B,
    long lda, long ldb, int k0, int tid)
{
    uint32_t base = sb + (uint32_t)(s * STG2);
    #pragma unroll
    for (int i = 0; i < 2; i++) {
        int idx = tid + i * 256;                 // 0..511
        int r = idx >> 2, cb = (idx & 3) << 4;
        cp16(base + (uint32_t)(r * LDSS + cb), A + (long)r * lda + k0 + (cb >> 1));
    }
    #pragma unroll
    for (int i = 0; i < 4; i++) {
        int idx = tid + i * 256;                 // 0..1023
        int r = idx >> 2, cb = (idx & 3) << 4;
        cp16(base + (uint32_t)(AB2 + r * LDSS + cb), B + (long)r * ldb + k0 + (cb >> 1));
    }
}

__device__ __forceinline__ void compute_stage_2(
    uint32_t sb, int s, int wm, int wn, int l, float acc[4][8][4])
{
    uint32_t As = sb + (uint32_t)(s * STG2);
    uint32_t Bs = As + AB2;
    uint32_t a_off = (uint32_t)((wm * 64 + (l & 15)) * LDSS + ((l >> 4) << 4));
    uint32_t b_off = (uint32_t)((wn * 64 + ((l >> 4) << 3) + (l & 7)) * LDSS
                                + (((l >> 3) & 1) << 4));
    #pragma unroll
    for (int kk = 0; kk < 2; kk++) {
        uint32_t kb = (uint32_t)(kk * 32);
        uint32_t ah[4][4], bh[8][2];
        #pragma unroll
        for (int m = 0; m < 4; m++)
            ldmx4(ah[m], As + a_off + m * (16 * LDSS) + kb);
        #pragma unroll
        for (int p = 0; p < 4; p++) {
            uint32_t r[4];
            ldmx4(r, Bs + b_off + p * (16 * LDSS) + kb);
            bh[2*p][0] = r[0]; bh[2*p][1] = r[1];
            bh[2*p+1][0] = r[2]; bh[2*p+1][1] = r[3];
        }
        #pragma unroll
        for (int m = 0; m < 4; m++)
            #pragma unroll
            for (int n = 0; n < 8; n++)
                mma16816h(acc[m][n], ah[m], bh[n]);
    }
}

template <int OB>
__device__ __forceinline__ void gemm256(
    const f16* __restrict__ a, long lda, const f16* __restrict__ b, long ldb,
    const float* __restrict__ R, void* __restrict__ Cv, long ldc,
    int K, int m0, int n0,
    const float* __restrict__ cs, const float* __restrict__ sn,
    const f16* __restrict__ G)
{
    constexpr int S = 3;
    extern __shared__ char smem[];
    uint32_t sb = smem_u32(smem);
    const int tid = threadIdx.x, wid = tid >> 5, l = tid & 31;
    const int wm = wid & 1, wn = wid >> 1;   // 2 x 4

    const f16* A = a + (long)m0 * lda;
    const f16* B = b + (long)n0 * ldb;

    float acc[4][8][4];
    #pragma unroll
    for (int m = 0; m < 4; m++)
        #pragma unroll
        for (int n = 0; n < 8; n++)
            #pragma unroll
            for (int i = 0; i < 4; i++) acc[m][n][i] = 0.f;

    const int nk = K >> 5;
    #pragma unroll
    for (int c = 0; c < S - 1; c++) {
        load_stage_2(sb, c, A, B, lda, ldb, c * 32, tid);
        CP_COMMIT();
    }
    int slot_c = 0, slot_p = S - 1;
    for (int c = 0; c < nk; c++) {
        cp_wait<S - 2>();
        __syncthreads();
        if (c + S - 1 < nk)
            load_stage_2(sb, slot_p, A, B, lda, ldb, (c + S - 1) * 32, tid);
        CP_COMMIT();
        compute_stage_2(sb, slot_c, wm, wn, l, acc);
        slot_c = (slot_c + 1 == S) ? 0 : slot_c + 1;
        slot_p = (slot_p + 1 == S) ? 0 : slot_p + 1;
    }

    const int row0 = m0 + wm * 64, col0 = n0 + wn * 64;
    #pragma unroll
    for (int m = 0; m < 4; m++) {
        int r0 = row0 + m * 16 + (l >> 2);
        #pragma unroll
        for (int n = 0; n < 8; n++) {
            int cc = col0 + n * 8 + (l & 3) * 2;   // even global column
            float2 v0 = make_float2(acc[m][n][0], acc[m][n][1]);
            float2 v1 = make_float2(acc[m][n][2], acc[m][n][3]);
            if (OB == 0) {
                float* C = (float*)Cv;
                if (R) {
                    float2 q0 = *(const float2*)(R + (long)r0 * ldc + cc);
                    float2 q1 = *(const float2*)(R + (long)(r0 + 8) * ldc + cc);
                    v0.x += q0.x; v0.y += q0.y; v1.x += q1.x; v1.y += q1.y;
                }
                *(float2*)(C + (long)r0 * ldc + cc)       = v0;
                *(float2*)(C + (long)(r0 + 8) * ldc + cc) = v1;
            } else if (OB == 1) {
                f16* C = (f16*)Cv;
                __half2 h0, h1;
                h0.x = __float2half(v0.x); h0.y = __float2half(v0.y);
                h1.x = __float2half(v1.x); h1.y = __float2half(v1.y);
                *(__half2*)(C + (long)r0 * ldc + cc)       = h0;
                *(__half2*)(C + (long)(r0 + 8) * ldc + cc) = h1;
            } else if (OB == 2) {
                // fused RoPE. cc even; (v.x, v.y) = (x[2j], x[2j+1]) of head.
                f16* C = (f16*)Cv;
                int hb = cc & ~127;
                int j  = (cc & 127) >> 1;
                float c0 = cs[(long)r0 * 64 + j];
                float s0 = sn[(long)r0 * 64 + j];
                C[(long)r0 * ldc + hb + j]      = __float2half(v0.x * c0 - v0.y * s0);
                C[(long)r0 * ldc + hb + 64 + j] = __float2half(v0.x * s0 + v0.y * c0);
                float c1 = cs[(long)(r0 + 8) * 64 + j];
                float s1 = sn[(long)(r0 + 8) * 64 + j];
                C[(long)(r0 + 8) * ldc + hb + j]      = __float2half(v1.x * c1 - v1.y * s1);
                C[(long)(r0 + 8) * ldc + hb + 64 + j] = __float2half(v1.x * s1 + v1.y * c1);
            } else {
                // OB == 3: out = silu(G) * result
                f16* C = (f16*)Cv;
                __half2 gp0 = *(const __half2*)(G + (long)r0 * ldc + cc);
                __half2 gp1 = *(const __half2*)(G + (long)(r0 + 8) * ldc + cc);
                float g0 = __half2float(gp0.x), g1 = __half2float(gp0.y);
                float g2 = __half2float(gp1.x), g3 = __half2float(gp1.y);
                __half2 h0, h1;
                h0.x = __float2half(v0.x * g0 / (1.0f + expf(-g0)));
                h0.y = __float2half(v0.y * g1 / (1.0f + expf(-g1)));
                h1.x = __float2half(v1.x * g2 / (1.0f + expf(-g2)));
                h1.y = __float2half(v1.y * g3 / (1.0f + expf(-g3)));
                *(__half2*)(C + (long)r0 * ldc + cc)       = h0;
                *(__half2*)(C + (long)(r0 + 8) * ldc + cc) = h1;
            }
        }
    }
}

// ---------------------------------------------------------------------------
// 256-thread GEMM wrapper kernels
// ---------------------------------------------------------------------------
__global__ __launch_bounds__(256, 1) void g256_f32out_kernel(
    const f16* a, long lda, const f16* b, long ldb,
    const float* R, float* C, long ldc, int K)
{
    gemm256<0>(a, lda, b, ldb, R, C, ldc, K,
               blockIdx.y * 128, blockIdx.x * 256, nullptr, nullptr, nullptr);
}

__global__ __launch_bounds__(256, 1) void g256_f16out_kernel(
    const f16* a, long lda, const f16* b, long ldb, f16* C, long ldc, int K)
{
    gemm256<1>(a, lda, b, ldb, nullptr, C, ldc, K,
               blockIdx.y * 128, blockIdx.x * 256, nullptr, nullptr, nullptr);
}

__global__ __launch_bounds__(256, 1) void g256_rope_kernel(
    const f16* a, long lda, const f16* b, long ldb,
    f16* C, long ldc, int K, const float* cs, const float* sn)
{
    gemm256<2>(a, lda, b, ldb, nullptr, C, ldc, K,
               blockIdx.y * 128, blockIdx.x * 256, cs, sn, nullptr);
}

__global__ __launch_bounds__(256, 1) void g256_silu_kernel(
    const f16* a, long lda, const f16* b, long ldb,
    f16* C, long ldc, int K, const f16* G)
{
    gemm256<3>(a, lda, b, ldb, nullptr, C, ldc, K,
               blockIdx.y * 128, blockIdx.x * 256, nullptr, nullptr, G);
}

__global__ __launch_bounds__(256, 1) void g256_scores_kernel()
{
    int z = blockIdx.z, b = z >> 4, h = z & 15, kh = h >> 1;
    const f16* A = g_qh + (long)b * SEQ * DMODEL + h * HD;
    const f16* B = g_kh + (long)b * SEQ * DKV + kh * HD;
    f16* C = g_sc + (long)z * SEQ * SEQ;
    gemm256<1>(A, DMODEL, B, DKV, nullptr, C, SEQ, HD,
               blockIdx.y * 128, blockIdx.x * 256, nullptr, nullptr, nullptr);
}

// ===========================================================================
// 128-thread fp16 GEMM (PV only; N=128 output per head)
// ===========================================================================
constexpr int MATB = 128 * LDSS;         // 10240
constexpr int SM1  = 3 * 2 * MATB;       // 61440

__device__ __forceinline__ void load_stage_h(
    uint32_t sb, int s, const f16* __restrict__ A, const f16* __restrict__ B,
    long lda, long ldb, int k0, int tid)
{
    uint32_t base = sb + (uint32_t)(s * 2 * MATB);
    #pragma unroll
    for (int i = 0; i < 4; i++) {
        int idx = tid + i * 128;
        int r = idx >> 2, cb = (idx & 3) << 4;
        uint32_t so = (uint32_t)(r * LDSS + cb);
        cp16(base + so,        A + (long)r * lda + k0 + (cb >> 1));
        cp16(base + MATB + so, B + (long)r * ldb + k0 + (cb >> 1));
    }
}

__device__ __forceinline__ void compute_stage_h(
    uint32_t sb, int s, int wm, int wn, int l, float acc[4][8][4])
{
    uint32_t As = sb + (uint32_t)(s * 2 * MATB);
    uint32_t Bs = As + MATB;
    uint32_t a_off = (uint32_t)((wm * 64 + (l & 15)) * LDSS + ((l >> 4) << 4));
    uint32_t b_off = (uint32_t)((wn * 64 + ((l >> 4) << 3) + (l & 7)) * LDSS
                                + (((l >> 3) & 1) << 4));
    #pragma unroll
    for (int kk = 0; kk < 2; kk++) {
        uint32_t kb = (uint32_t)(kk * 32);
        uint32_t ah[4][4], bh[8][2];
        #pragma unroll
        for (int m = 0; m < 4; m++)
            ldmx4(ah[m], As + a_off + m * (16 * LDSS) + kb);
        #pragma unroll
        for (int p = 0; p < 4; p++) {
            uint32_t r[4];
            ldmx4(r, Bs + b_off + p * (16 * LDSS) + kb);
            bh[2*p][0] = r[0]; bh[2*p][1] = r[1];
            bh[2*p+1][0] = r[2]; bh[2*p+1][1] = r[3];
        }
        #pragma unroll
        for (int m = 0; m < 4; m++)
            #pragma unroll
            for (int n = 0; n < 8; n++)
                mma16816h(acc[m][n], ah[m], bh[n]);
    }
}

__global__ __launch_bounds__(128) void gemm_pv_kernel()
{
    int z = blockIdx.z, b = z >> 4, h = z & 15, kh = h >> 1;
    const f16* A = g_ph + (long)z * SEQ * SEQ + (long)blockIdx.y * 128 * SEQ;
    const f16* B = g_vth + (long)(b * NKV + kh) * HD * SEQ;
    f16* C = g_ctxh + (long)b * SEQ * DMODEL + h * HD;

    constexpr int S = 3;
    extern __shared__ char smem[];
    uint32_t sb = smem_u32(smem);
    const int tid = threadIdx.x, wid = tid >> 5, l = tid & 31;
    const int wm = wid & 1, wn = wid >> 1;

    float acc[4][8][4];
    #pragma unroll
    for (int m = 0; m < 4; m++)
        #pragma unroll
        for (int n = 0; n < 8; n++)
            #pragma unroll
            for (int i = 0; i < 4; i++) acc[m][n][i] = 0.f;

    const int nk = SEQ >> 5;
    #pragma unroll
    for (int c = 0; c < S - 1; c++) {
        load_stage_h(sb, c, A, B, SEQ, SEQ, c * 32, tid);
        CP_COMMIT();
    }
    int slot_c = 0, slot_p = S - 1;
    for (int c = 0; c < nk; c++) {
        cp_wait<S - 2>();
        __syncthreads();
        if (c + S - 1 < nk)
            load_stage_h(sb, slot_p, A, B, SEQ, SEQ, (c + S - 1) * 32, tid);
        CP_COMMIT();
        compute_stage_h(sb, slot_c, wm, wn, l, acc);
        slot_c = (slot_c + 1 == S) ? 0 : slot_c + 1;
        slot_p = (slot_p + 1 == S) ? 0 : slot_p + 1;
    }

    const int row0 = blockIdx.y * 128 + wm * 64, col0 = wn * 64;
    #pragma unroll
    for (int m = 0; m < 4; m++) {
        int r0 = row0 + m * 16 + (l >> 2);
        #pragma unroll
        for (int n = 0; n < 8; n++) {
            int cc = col0 + n * 8 + (l & 3) * 2;
            __half2 h0, h1;
            h0.x = __float2half(acc[m][n][0]); h0.y = __float2half(acc[m][n][1]);
            h1.x = __float2half(acc[m][n][2]); h1.y = __float2half(acc[m][n][3]);
            *(__half2*)(C + (long)r0 * DMODEL + cc)       = h0;
            *(__half2*)(C + (long)(r0 + 8) * DMODEL + cc) = h1;
        }
    }
}

// ---------------------------------------------------------------------------
// Reductions
// ---------------------------------------------------------------------------
__device__ __forceinline__ float block_reduce_sum(float v)
{
    __shared__ float red[32];
    int lid = threadIdx.x & 31, wid = threadIdx.x >> 5;
    #pragma unroll
    for (int o = 16; o; o >>= 1) v += __shfl_xor_sync(0xffffffffu, v, o);
    if (lid == 0) red[wid] = v;
    __syncthreads();
    v = (threadIdx.x < 8) ? red[threadIdx.x] : 0.f;
    if (wid == 0) {
        #pragma unroll
        for (int o = 4; o; o >>= 1) v += __shfl_xor_sync(0xffffffffu, v, o);
        if (lid == 0) red[0] = v;
    }
    __syncthreads();
    return red[0];
}
__device__ __forceinline__ float block_reduce_max(float v)
{
    __shared__ float red[32];
    int lid = threadIdx.x & 31, wid = threadIdx.x >> 5;
    #pragma unroll
    for (int o = 16; o; o >>= 1) v = fmaxf(v, __shfl_xor_sync(0xffffffffu, v, o));
    if (lid == 0) red[wid] = v;
    __syncthreads();
    v = (threadIdx.x < 8) ? red[threadIdx.x] : -INFINITY;
    if (wid == 0) {
        #pragma unroll
        for (int o = 4; o; o >>= 1) v = fmaxf(v, __shfl_xor_sync(0xffffffffu, v, o));
        if (lid == 0) red[0] = v;
    }
    __syncthreads();
    return red[0];
}

// ---------------------------------------------------------------------------
// RMSNorm -> fp16
// ---------------------------------------------------------------------------
__global__ __launch_bounds__(256) void rmsnorm_f16_kernel(
    const float* __restrict__ x, const float* __restrict__ w,
    f16* __restrict__ oh)
{
    long row = blockIdx.x;
    const float* xr = x + row * DMODEL;
    float vals[8];
    float ss = 0.f;
    #pragma unroll
    for (int i = 0; i < 8; i++) {
        int idx = threadIdx.x + i * 256;
        vals[i] = xr[idx];
        ss = fmaf(vals[i], vals[i], ss);
    }
    float total = block_reduce_sum(ss);
    float rstd = rsqrtf(total * (1.0f / DMODEL) + EPSV);
    #pragma unroll
    for (int i = 0; i < 8; i++) {
        int idx = threadIdx.x + i * 256;
        oh[row * DMODEL + idx] = __float2half(vals[i] * rstd * w[idx]);
    }
}

// ---------------------------------------------------------------------------
// Weight transpose: in [RI, CI] fp32 -> out [CI, RI] fp16
// ---------------------------------------------------------------------------
__global__ __launch_bounds__(256) void transpose_f16_kernel(
    const float* __restrict__ in, f16* __restrict__ oh, int RI, int CI)
{
    __shared__ float t[32][33];
    int tx = threadIdx.x & 31, ty = threadIdx.x >> 5;
    int r0 = blockIdx.y * 32, c0 = blockIdx.x * 32;
    #pragma unroll
    for (int i = 0; i < 4; i++)
        t[ty + i * 8][tx] = in[(long)(r0 + ty + i * 8) * CI + c0 + tx];
    __syncthreads();
    #pragma unroll
    for (int i = 0; i < 4; i++)
        oh[(long)(c0 + ty + i * 8) * RI + r0 + tx] =
            __float2half(t[tx][ty + i * 8]);
}

// V transpose: g_v [b, s, kh*128+d] -> g_vth [(b*8+kh)][d][s] fp16
__global__ __launch_bounds__(256) void vT_kernel()
{
    __shared__ float t[32][33];
    int z = blockIdx.z;
    int b = z >> 3, kh = z & 7;
    const float* in = g_v + (long)b * SEQ * DKV + kh * HD;
    f16* oh = g_vth + (long)z * HD * SEQ;
    int tx = threadIdx.x & 31, ty = threadIdx.x >> 5;
    int s0 = blockIdx.y * 32, d0 = blockIdx.x * 32;
    #pragma unroll
    for (int i = 0; i < 4; i++)
        t[ty + i * 8][tx] = in[(long)(s0 + ty + i * 8) * DKV + d0 + tx];
    __syncthreads();
    #pragma unroll
    for (int i = 0; i < 4; i++)
        oh[(long)(d0 + ty + i * 8) * SEQ + s0 + tx] =
            __float2half(t[tx][ty + i * 8]);
}

// ---------------------------------------------------------------------------
// Softmax (scale + mask), fp16 in -> fp16 out
// ---------------------------------------------------------------------------
__global__ __launch_bounds__(256) void softmax_kernel(const float* __restrict__ mask)
{
    int z = blockIdx.y;
    int b = z >> 4;
    long row = blockIdx.x;
    const f16* srow = g_sc + ((long)z * SEQ + row) * SEQ;
    const float* mrow = mask + ((long)b * SEQ + row) * SEQ;
    f16* phr = g_ph + ((long)z * SEQ + row) * SEQ;

    float v[8];
    float mx = -INFINITY;
    #pragma unroll
    for (int i = 0; i < 8; i++) {
        int idx = threadIdx.x + i * 256;
        v[i] = fmaf(__half2float(srow[idx]), SM_SCALE, mrow[idx]);
        mx = fmaxf(mx, v[i]);
    }
    float bm = block_reduce_max(mx);
    float sum = 0.f;
    #pragma unroll
    for (int i = 0; i < 8; i++) {
        v[i] = expf(v[i] - bm);
        sum += v[i];
    }
    float total = block_reduce_sum(sum);
    float inv = 1.0f / total;
    #pragma unroll
    for (int i = 0; i < 8; i++) {
        int idx = threadIdx.x + i * 256;
        phr[idx] = __float2half(v[i] * inv);
    }
}

// ---------------------------------------------------------------------------
// Launch
// ---------------------------------------------------------------------------
extern "C" void kernel_launch(void* const* d_in, const int* in_sizes, int n_in,
                              void* d_out, int out_size)
{
    const float* hs   = (const float*)d_in[0];
    const float* cosp = (const float*)d_in[1];
    const float* sinp = (const float*)d_in[2];
    const float* mask = (const float*)d_in[3];
    const float* wq   = (const float*)d_in[4];
    const float* wk   = (const float*)d_in[5];
    const float* wv   = (const float*)d_in[6];
    const float* wo   = (const float*)d_in[7];
    const float* wg   = (const float*)d_in[8];
    const float* wu   = (const float*)d_in[9];
    const float* wd   = (const float*)d_in[10];
    const float* ln1  = (const float*)d_in[11];
    const float* ln2  = (const float*)d_in[12];
    float* out = (float*)d_out;

    cudaFuncSetAttribute(g256_f32out_kernel,
                         cudaFuncAttributeMaxDynamicSharedMemorySize, SM2);
    cudaFuncSetAttribute(g256_f16out_kernel,
                         cudaFuncAttributeMaxDynamicSharedMemorySize, SM2);
    cudaFuncSetAttribute(g256_rope_kernel,
                         cudaFuncAttributeMaxDynamicSharedMemorySize, SM2);
    cudaFuncSetAttribute(g256_silu_kernel,
                         cudaFuncAttributeMaxDynamicSharedMemorySize, SM2);
    cudaFuncSetAttribute(g256_scores_kernel,
                         cudaFuncAttributeMaxDynamicSharedMemorySize, SM2);
    cudaFuncSetAttribute(gemm_pv_kernel,
                         cudaFuncAttributeMaxDynamicSharedMemorySize, SM1);

    f16 *x1h, *qh, *kh, *ctxh, *x2h, *g16, *mh;
    f16 *wqt, *wkt, *wvt, *wot, *wgt, *wut, *wdt;
    float *v, *h2;
    cudaGetSymbolAddress((void**)&x1h, g_x1h);
    cudaGetSymbolAddress((void**)&qh,  g_qh);
    cudaGetSymbolAddress((void**)&kh,  g_kh);
    cudaGetSymbolAddress((void**)&ctxh,g_ctxh);
    cudaGetSymbolAddress((void**)&x2h, g_x2h);
    cudaGetSymbolAddress((void**)&g16, g_g16);
    cudaGetSymbolAddress((void**)&mh,  g_mh);
    cudaGetSymbolAddress((void**)&wqt, g_wqt);
    cudaGetSymbolAddress((void**)&wkt, g_wkt);
    cudaGetSymbolAddress((void**)&wvt, g_wvt);
    cudaGetSymbolAddress((void**)&wot, g_wot);
    cudaGetSymbolAddress((void**)&wgt, g_wgt);
    cudaGetSymbolAddress((void**)&wut, g_wut);
    cudaGetSymbolAddress((void**)&wdt, g_wdt);
    cudaGetSymbolAddress((void**)&v,   g_v);
    cudaGetSymbolAddress((void**)&h2,  g_h2);

    // 1) x1 = rmsnorm(hs) -> fp16
    rmsnorm_f16_kernel<<<TOK, 256>>>(hs, ln1, x1h);

    // 2) weight transposes -> fp16 [N,K]
    transpose_f16_kernel<<<dim3(DMODEL/32, DMODEL/32), 256>>>(wq, wqt, DMODEL, DMODEL);
    transpose_f16_kernel<<<dim3(DKV/32,    DMODEL/32), 256>>>(wk, wkt, DMODEL, DKV);
    transpose_f16_kernel<<<dim3(DKV/32,    DMODEL/32), 256>>>(wv, wvt, DMODEL, DKV);
    transpose_f16_kernel<<<dim3(DMODEL/32, DMODEL/32), 256>>>(wo, wot, DMODEL, DMODEL);
    transpose_f16_kernel<<<dim3(DFF/32,    DMODEL/32), 256>>>(wg, wgt, DMODEL, DFF);
    transpose_f16_kernel<<<dim3(DFF/32,    DMODEL/32), 256>>>(wu, wut, DMODEL, DFF);
    transpose_f16_kernel<<<dim3(DMODEL/32, DFF/32),    256>>>(wd, wdt, DFF, DMODEL);

    // 3) Q/K projections with fused RoPE -> fp16; V projection -> fp32
    g256_rope_kernel<<<dim3(DMODEL/256, TOK/128), 256, SM2>>>(
        x1h, DMODEL, wqt, DMODEL, qh, DMODEL, DMODEL, cosp, sinp);
    g256_rope_kernel<<<dim3(DKV/256, TOK/128), 256, SM2>>>(
        x1h, DMODEL, wkt, DMODEL, kh, DKV, DMODEL, cosp, sinp);
    g256_f32out_kernel<<<dim3(DKV/256, TOK/128), 256, SM2>>>(
        x1h, DMODEL, wvt, DMODEL, nullptr, v, DKV, DMODEL);

    // 4) V transpose -> fp16
    vT_kernel<<<dim3(HD/32, SEQ/32, BATCH*NKV), 256>>>();

    // 5) scores = Q K^T -> fp16
    g256_scores_kernel<<<dim3(SEQ/256, SEQ/128, BATCH*NHEADS), 256, SM2>>>();

    // 6) softmax -> P fp16
    softmax_kernel<<<dim3(SEQ, BATCH*NHEADS), 256>>>(mask);

    // 7) ctx = P V -> fp16
    gemm_pv_kernel<<<dim3(1, SEQ/128, BATCH*NHEADS), 128, SM1>>>();

    // 8) h2 = hs + ctx @ wo
    g256_f32out_kernel<<<dim3(DMODEL/256, TOK/128), 256, SM2>>>(
        ctxh, DMODEL, wot, DMODEL, hs, h2, DMODEL, DMODEL);

    // 9) x2 = rmsnorm(h2) -> fp16
    rmsnorm_f16_kernel<<<TOK, 256>>>(h2, ln2, x2h);

    // 10) MLP: gate, then up with fused SwiGLU
    g256_f16out_kernel<<<dim3(DFF/256, TOK/128), 256, SM2>>>(
        x2h, DMODEL, wgt, DMODEL, g16, DFF, DMODEL);
    g256_silu_kernel<<<dim3(DFF/256, TOK/128), 256, SM2>>>(
        x2h, DMODEL, wut, DMODEL, mh, DFF, DMODEL, g16);

    // 11) out = h2 + m @ wd
    g256_f32out_kernel<<<dim3(DMODEL/256, TOK/128), 256, SM2>>>(
        mh, DFF, wdt, DFF, h2, out, DMODEL, DFF);
}